// round 1
// baseline (speedup 1.0000x reference)
#include <cuda_runtime.h>
#include <math.h>
#include <stdint.h>

// ---------------- problem constants ----------------
#define BB 4
#define TT 4096
#define DD 1024
#define KK 128
#define HH 8
#define KH 16
#define KER 4
#define MM 4096          // mlp hidden
#define C2K 256          // 2*K
#define NT (BB*TT)       // 16384 rows

// ---------------- scratch (static device, no allocs) ----------------
__device__ float g_xn[(size_t)NT*DD];
__device__ float g_beta0[(size_t)NT*C2K];
__device__ float g_pm[(size_t)NT*C2K];
__device__ float g_bR[(size_t)BB*KK*TT];
__device__ float g_bI[(size_t)BB*KK*TT];
__device__ float g_cR[(size_t)BB*KK*TT];
__device__ float g_cI[(size_t)BB*KK*TT];
__device__ float g_gate[(size_t)NT*DD];
__device__ float g_x1[(size_t)NT*DD];
__device__ float g_y[(size_t)NT*DD];
__device__ float g_h1[(size_t)NT*MM];

__device__ __forceinline__ float sigmf(float x) { return 1.f / (1.f + __expf(-x)); }

// ---------------- LayerNorm: one block per row (D=1024, 256 thr) ----------------
__global__ void ten_ln_kernel(const float* __restrict__ x,
                              const float* __restrict__ gw,
                              const float* __restrict__ bw,
                              float* __restrict__ y)
{
    const int row = blockIdx.x;
    const int tid = threadIdx.x;
    const float4* xr = (const float4*)(x + (size_t)row * DD);
    float4 v = xr[tid];
    float s = v.x + v.y + v.z + v.w;
    float q = v.x*v.x + v.y*v.y + v.z*v.z + v.w*v.w;
    #pragma unroll
    for (int o = 16; o > 0; o >>= 1) {
        s += __shfl_xor_sync(0xffffffffu, s, o);
        q += __shfl_xor_sync(0xffffffffu, q, o);
    }
    __shared__ float ss[8], sq[8];
    const int w = tid >> 5, l = tid & 31;
    if (l == 0) { ss[w] = s; sq[w] = q; }
    __syncthreads();
    float st = 0.f, qt = 0.f;
    #pragma unroll
    for (int i = 0; i < 8; i++) { st += ss[i]; qt += sq[i]; }
    const float mean = st * (1.f / DD);
    const float var  = qt * (1.f / DD) - mean * mean;
    const float rstd = rsqrtf(var + 1e-5f);
    float4 g4 = ((const float4*)gw)[tid];
    float4 b4 = ((const float4*)bw)[tid];
    float4 o;
    o.x = (v.x - mean) * rstd * g4.x + b4.x;
    o.y = (v.y - mean) * rstd * g4.y + b4.y;
    o.z = (v.z - mean) * rstd * g4.z + b4.z;
    o.w = (v.w - mean) * rstd * g4.w + b4.w;
    ((float4*)(y + (size_t)row * DD))[tid] = o;
}

// ---------------- SGEMM C[M,N] = A[M,K] * B[N,K]^T  (both K-contiguous) --------
// 128x128 block tile, BK=16, 256 threads, 8x8 per thread. Fused epilogues.
enum { EPI_NONE = 0, EPI_GATE = 1, EPI_SILU_BIAS = 2, EPI_BIAS_RES = 3 };

template<int EPI>
__global__ void __launch_bounds__(256, 2)
ten_sgemm_nt(const float* __restrict__ A, const float* __restrict__ B,
             float* __restrict__ C, int M, int N, int K,
             const float* __restrict__ aux0,   // GATE: g scratch | SILU_BIAS/BIAS_RES: bias[N]
             const float* __restrict__ aux1,   // GATE: gate_b[N]
             const float* __restrict__ aux2)   // GATE/BIAS_RES: residual [M,N]
{
    __shared__ float As[16][128];
    __shared__ float Bs[16][128];
    const int tid = threadIdx.x;
    const int bm = blockIdx.y, bn = blockIdx.x;
    const float* Ab = A + (size_t)bm * 128 * K;
    const float* Bb = B + (size_t)bn * 128 * K;

    const int lr = tid >> 2;          // 0..63
    const int lc = (tid & 3) * 4;     // 0,4,8,12
    const int ty = tid >> 4, tx = tid & 15;

    float acc[8][8];
    #pragma unroll
    for (int i = 0; i < 8; i++)
        #pragma unroll
        for (int j = 0; j < 8; j++) acc[i][j] = 0.f;

    for (int k0 = 0; k0 < K; k0 += 16) {
        #pragma unroll
        for (int h = 0; h < 2; h++) {
            const int row = lr + h * 64;
            float4 a = *(const float4*)(Ab + (size_t)row * K + k0 + lc);
            As[lc + 0][row] = a.x; As[lc + 1][row] = a.y;
            As[lc + 2][row] = a.z; As[lc + 3][row] = a.w;
            float4 b = *(const float4*)(Bb + (size_t)row * K + k0 + lc);
            Bs[lc + 0][row] = b.x; Bs[lc + 1][row] = b.y;
            Bs[lc + 2][row] = b.z; Bs[lc + 3][row] = b.w;
        }
        __syncthreads();
        #pragma unroll
        for (int kk = 0; kk < 16; kk++) {
            float4 a0 = *(const float4*)&As[kk][ty * 8];
            float4 a1 = *(const float4*)&As[kk][ty * 8 + 4];
            float4 b0 = *(const float4*)&Bs[kk][tx * 8];
            float4 b1 = *(const float4*)&Bs[kk][tx * 8 + 4];
            float ar[8] = {a0.x, a0.y, a0.z, a0.w, a1.x, a1.y, a1.z, a1.w};
            float br[8] = {b0.x, b0.y, b0.z, b0.w, b1.x, b1.y, b1.z, b1.w};
            #pragma unroll
            for (int i = 0; i < 8; i++)
                #pragma unroll
                for (int j = 0; j < 8; j++)
                    acc[i][j] = fmaf(ar[i], br[j], acc[i][j]);
        }
        __syncthreads();
    }

    const int m0 = bm * 128 + ty * 8;
    const int n0 = bn * 128 + tx * 8;
    #pragma unroll
    for (int i = 0; i < 8; i++) {
        const size_t rowoff = (size_t)(m0 + i) * N;
        #pragma unroll
        for (int jv = 0; jv < 2; jv++) {
            const int n = n0 + jv * 4;
            float4 r;
            r.x = acc[i][jv * 4 + 0]; r.y = acc[i][jv * 4 + 1];
            r.z = acc[i][jv * 4 + 2]; r.w = acc[i][jv * 4 + 3];
            if (EPI == EPI_GATE) {
                float4 g  = *(const float4*)(aux0 + rowoff + n);
                float4 gb = *(const float4*)(aux1 + n);
                float4 xr = *(const float4*)(aux2 + rowoff + n);
                r.x = xr.x + sigmf(g.x + gb.x) * r.x;
                r.y = xr.y + sigmf(g.y + gb.y) * r.y;
                r.z = xr.z + sigmf(g.z + gb.z) * r.z;
                r.w = xr.w + sigmf(g.w + gb.w) * r.w;
            } else if (EPI == EPI_SILU_BIAS) {
                float4 bb = *(const float4*)(aux0 + n);
                float t0_ = r.x + bb.x; r.x = t0_ * sigmf(t0_);
                float t1_ = r.y + bb.y; r.y = t1_ * sigmf(t1_);
                float t2_ = r.z + bb.z; r.z = t2_ * sigmf(t2_);
                float t3_ = r.w + bb.w; r.w = t3_ * sigmf(t3_);
            } else if (EPI == EPI_BIAS_RES) {
                float4 bb = *(const float4*)(aux0 + n);
                float4 xr = *(const float4*)(aux2 + rowoff + n);
                r.x = xr.x + r.x + bb.x;
                r.y = xr.y + r.y + bb.y;
                r.z = xr.z + r.z + bb.z;
                r.w = xr.w + r.w + bb.w;
            }
            *(float4*)(C + rowoff + n) = r;
        }
    }
}

// ---------------- depthwise causal conv(ker=4) + bias + SiLU + mem inject,
// writes transposed planar [B,K,T] real / imag for the scan -------------------
__global__ void __launch_bounds__(256)
ten_conv_mem_kernel(const float* __restrict__ beta0,
                    const float* __restrict__ pm,
                    const float* __restrict__ conv_w,
                    const float* __restrict__ conv_b,
                    const float* __restrict__ mem_gate,
                    float* __restrict__ bR, float* __restrict__ bI)
{
    const int b   = blockIdx.z;
    const int cg0 = blockIdx.y * 32;  // channel group (of 256)
    const int t0  = blockIdx.x * 64;  // time tile
    __shared__ float sb[67][33];
    __shared__ float sp[64][33];
    const int tid = threadIdx.x;

    for (int i = tid; i < 67 * 32; i += 256) {
        const int r = i >> 5, c = i & 31;
        const int t = t0 + r - 3;
        sb[r][c] = (t >= 0) ? beta0[((size_t)(b * TT + t)) * C2K + cg0 + c] : 0.f;
    }
    for (int i = tid; i < 64 * 32; i += 256) {
        const int r = i >> 5, c = i & 31;
        sp[r][c] = pm[((size_t)(b * TT + t0 + r)) * C2K + cg0 + c];
    }
    __syncthreads();

    const float mg = 1.f / (1.f + expf(-mem_gate[0]));
    const int cl = tid >> 3;             // 0..31 local channel
    const int tg = (tid & 7) * 8;        // local time start
    const int cglob = cg0 + cl;
    const float w0 = conv_w[cglob * 4 + 0];
    const float w1 = conv_w[cglob * 4 + 1];
    const float w2 = conv_w[cglob * 4 + 2];
    const float w3 = conv_w[cglob * 4 + 3];
    const float cb = conv_b[cglob];
    const int k = cglob & (KK - 1);
    float* dst = ((cglob < KK) ? bR : bI) + ((size_t)(b * KK + k)) * TT + t0 + tg;
    #pragma unroll
    for (int j = 0; j < 8; j++) {
        const int r = tg + j;
        float v = sb[r][cl] * w0 + sb[r + 1][cl] * w1 + sb[r + 2][cl] * w2 + sb[r + 3][cl] * w3 + cb;
        v = v * (1.f / (1.f + __expf(-v)));     // SiLU
        v += mg * sp[r][cl];
        dst[j] = v;
    }
}

// ---------------- complex first-order recurrence scan over T=4096 --------------
// one block per (b,k): c[t] = lambda*c[t-1] + beta[t], lambda = sigmoid(ld)*e^{i f}
__global__ void __launch_bounds__(256)
ten_scan_kernel(const float* __restrict__ bR, const float* __restrict__ bI,
                const float* __restrict__ log_decay, const float* __restrict__ freq,
                float* __restrict__ cR, float* __restrict__ cI)
{
    const int bk = blockIdx.x;
    const int k = bk & (KK - 1);
    const float mag = 1.f / (1.f + expf(-log_decay[k]));
    float snf, csf;
    sincosf(freq[k], &snf, &csf);
    const float lr = mag * csf, li = mag * snf;
    const int tid = threadIdx.x;
    const size_t base = (size_t)bk * TT + tid * 16;

    float xr[16], xi[16];
    #pragma unroll
    for (int v = 0; v < 4; v++) {
        float4 a = *(const float4*)(bR + base + v * 4);
        xr[v*4+0] = a.x; xr[v*4+1] = a.y; xr[v*4+2] = a.z; xr[v*4+3] = a.w;
        float4 c = *(const float4*)(bI + base + v * 4);
        xi[v*4+0] = c.x; xi[v*4+1] = c.y; xi[v*4+2] = c.z; xi[v*4+3] = c.w;
    }

    // serial chunk with zero init; keep partial states in place
    float cr = 0.f, ci = 0.f;
    #pragma unroll
    for (int j = 0; j < 16; j++) {
        float nr = fmaf(lr, cr, fmaf(-li, ci, xr[j]));
        float ni = fmaf(lr, ci, fmaf( li, cr, xi[j]));
        cr = nr; ci = ni;
        xr[j] = cr; xi[j] = ci;
    }

    // F = lambda^16 via 4 squarings
    float fr = lr, fi = li;
    #pragma unroll
    for (int s = 0; s < 4; s++) {
        float nr = fr * fr - fi * fi;
        float ni = 2.f * fr * fi;
        fr = nr; fi = ni;
    }

    // Hillis-Steele inclusive scan of (gain, offset) affine elements
    __shared__ float sgr[256], sgi[256], sor[256], soi[256];
    sgr[tid] = fr; sgi[tid] = fi; sor[tid] = cr; soi[tid] = ci;
    __syncthreads();
    for (int d = 1; d < 256; d <<= 1) {
        float ngr = 0.f, ngi = 0.f, nor_ = 0.f, noi_ = 0.f;
        if (tid >= d) {
            const float pgr = sgr[tid - d], pgi = sgi[tid - d];
            const float por = sor[tid - d], poi = soi[tid - d];
            const float gr = sgr[tid], gi = sgi[tid];
            const float orr = sor[tid], oii = soi[tid];
            ngr  = gr * pgr - gi * pgi;
            ngi  = gr * pgi + gi * pgr;
            nor_ = gr * por - gi * poi + orr;
            noi_ = gr * poi + gi * por + oii;
        }
        __syncthreads();
        if (tid >= d) { sgr[tid] = ngr; sgi[tid] = ngi; sor[tid] = nor_; soi[tid] = noi_; }
        __syncthreads();
    }
    const float pr = (tid > 0) ? sor[tid - 1] : 0.f;
    const float pi = (tid > 0) ? soi[tid - 1] : 0.f;

    // out[j] = partial[j] + lambda^{j+1} * prefix
    float lpr = lr, lpi = li;
    #pragma unroll
    for (int j = 0; j < 16; j++) {
        xr[j] = fmaf(lpr, pr, fmaf(-lpi, pi, xr[j]));
        xi[j] = fmaf(lpr, pi, fmaf( lpi, pr, xi[j]));
        float nr = lpr * lr - lpi * li;
        float ni = lpr * li + lpi * lr;
        lpr = nr; lpi = ni;
    }
    #pragma unroll
    for (int v = 0; v < 4; v++) {
        float4 a = {xr[v*4+0], xr[v*4+1], xr[v*4+2], xr[v*4+3]};
        *(float4*)(cR + base + v * 4) = a;
        float4 c = {xi[v*4+0], xi[v*4+1], xi[v*4+2], xi[v*4+3]};
        *(float4*)(cI + base + v * 4) = c;
    }
}

// ---------------- per-head 16x16 coupling + transpose into eig [B,T,2K] --------
__global__ void __launch_bounds__(256)
ten_coupling_kernel(const float* __restrict__ cR, const float* __restrict__ cI,
                    const float* __restrict__ coupling, float* __restrict__ eig)
{
    const int b = blockIdx.z, h = blockIdx.y;
    const int t0 = blockIdx.x * 256;
    const int tid = threadIdx.x;
    __shared__ float sr[16][256];
    __shared__ float si[16][256];
    __shared__ float w[16][16];
    w[tid >> 4][tid & 15] = coupling[h * 256 + tid];
    #pragma unroll
    for (int kk = 0; kk < 16; kk++) {
        const size_t src = ((size_t)(b * KK + h * 16 + kk)) * TT + t0 + tid;
        sr[kk][tid] = cR[src];
        si[kk][tid] = cI[src];
    }
    __syncthreads();
    float orr[16], oii[16];
    #pragma unroll
    for (int j = 0; j < 16; j++) { orr[j] = 0.f; oii[j] = 0.f; }
    #pragma unroll
    for (int kk = 0; kk < 16; kk++) {
        const float vr = sr[kk][tid];
        const float vi = si[kk][tid];
        #pragma unroll
        for (int j = 0; j < 16; j++) {
            orr[j] = fmaf(w[j][kk], vr, orr[j]);
            oii[j] = fmaf(w[j][kk], vi, oii[j]);
        }
    }
    const size_t dst = ((size_t)(b * TT + t0 + tid)) * C2K + h * 16;
    #pragma unroll
    for (int j = 0; j < 16; j += 4) {
        float4 v = {orr[j], orr[j+1], orr[j+2], orr[j+3]};
        *(float4*)(eig + dst + j) = v;
        float4 u = {oii[j], oii[j+1], oii[j+2], oii[j+3]};
        *(float4*)(eig + dst + KK + j) = u;
    }
}

// ---------------- launch --------------------------------------------------------
extern "C" void kernel_launch(void* const* d_in, const int* in_sizes, int n_in,
                              void* d_out, int out_size)
{
    const float* x          = (const float*)d_in[0];
    const float* prev_eig   = (const float*)d_in[1];
    const float* in_proj_w  = (const float*)d_in[2];
    const float* conv_w     = (const float*)d_in[3];
    const float* conv_b     = (const float*)d_in[4];
    const float* mem_gate   = (const float*)d_in[5];
    const float* mem_proj_w = (const float*)d_in[6];
    const float* log_decay  = (const float*)d_in[7];
    const float* frequency  = (const float*)d_in[8];
    const float* coupling   = (const float*)d_in[9];
    const float* out_proj_w = (const float*)d_in[10];
    const float* gate_w     = (const float*)d_in[11];
    const float* gate_b     = (const float*)d_in[12];
    const float* mlp_w1     = (const float*)d_in[13];
    const float* mlp_b1     = (const float*)d_in[14];
    const float* mlp_w2     = (const float*)d_in[15];
    const float* mlp_b2     = (const float*)d_in[16];
    const float* n1_g       = (const float*)d_in[17];
    const float* n1_b       = (const float*)d_in[18];
    const float* n2_g       = (const float*)d_in[19];
    const float* n2_b       = (const float*)d_in[20];

    float* out_x2  = (float*)d_out;
    float* out_eig = out_x2 + (size_t)NT * DD;

    float *xn, *beta0, *pm, *bRp, *bIp, *cRp, *cIp, *gate, *x1, *y, *h1;
    cudaGetSymbolAddress((void**)&xn,    g_xn);
    cudaGetSymbolAddress((void**)&beta0, g_beta0);
    cudaGetSymbolAddress((void**)&pm,    g_pm);
    cudaGetSymbolAddress((void**)&bRp,   g_bR);
    cudaGetSymbolAddress((void**)&bIp,   g_bI);
    cudaGetSymbolAddress((void**)&cRp,   g_cR);
    cudaGetSymbolAddress((void**)&cIp,   g_cI);
    cudaGetSymbolAddress((void**)&gate,  g_gate);
    cudaGetSymbolAddress((void**)&x1,    g_x1);
    cudaGetSymbolAddress((void**)&y,     g_y);
    cudaGetSymbolAddress((void**)&h1,    g_h1);

    // 1) LN1
    ten_ln_kernel<<<NT, 256>>>(x, n1_g, n1_b, xn);

    // 2) beta0 = xn @ in_proj_w^T   [16384,256]
    {
        dim3 g(C2K / 128, NT / 128);
        ten_sgemm_nt<EPI_NONE><<<g, 256>>>(xn, in_proj_w, beta0, NT, C2K, DD,
                                           nullptr, nullptr, nullptr);
    }
    // 3) pm = prev_eig @ mem_proj_w^T  [16384,256]
    {
        dim3 g(C2K / 128, NT / 128);
        ten_sgemm_nt<EPI_NONE><<<g, 256>>>(prev_eig, mem_proj_w, pm, NT, C2K, C2K,
                                           nullptr, nullptr, nullptr);
    }
    // 4) conv + SiLU + mem inject -> planar [B,K,T] real/imag
    ten_conv_mem_kernel<<<dim3(TT / 64, C2K / 32, BB), 256>>>(
        beta0, pm, conv_w, conv_b, mem_gate, bRp, bIp);

    // 5) complex recurrence scan (replaces FFT conv)
    ten_scan_kernel<<<BB * KK, 256>>>(bRp, bIp, log_decay, frequency, cRp, cIp);

    // 6) coupling + transpose -> eig output region [B,T,2K]
    ten_coupling_kernel<<<dim3(TT / 256, HH, BB), 256>>>(cRp, cIp, coupling, out_eig);

    // 7) g = xn @ gate_w^T  [16384,1024]
    {
        dim3 g(DD / 128, NT / 128);
        ten_sgemm_nt<EPI_NONE><<<g, 256>>>(xn, gate_w, gate, NT, DD, DD,
                                           nullptr, nullptr, nullptr);
    }
    // 8) x1 = x + sigmoid(g + gate_b) * (eig @ out_proj_w^T)
    {
        dim3 g(DD / 128, NT / 128);
        ten_sgemm_nt<EPI_GATE><<<g, 256>>>(out_eig, out_proj_w, x1, NT, DD, C2K,
                                           gate, gate_b, x);
    }
    // 9) LN2
    ten_ln_kernel<<<NT, 256>>>(x1, n2_g, n2_b, y);

    // 10) h1 = silu(y @ mlp_w1^T + b1)   [16384,4096]
    {
        dim3 g(MM / 128, NT / 128);
        ten_sgemm_nt<EPI_SILU_BIAS><<<g, 256>>>(y, mlp_w1, h1, NT, MM, DD,
                                                mlp_b1, nullptr, nullptr);
    }
    // 11) x2 = x1 + h1 @ mlp_w2^T + b2  -> output
    {
        dim3 g(DD / 128, NT / 128);
        ten_sgemm_nt<EPI_BIAS_RES><<<g, 256>>>(h1, mlp_w2, out_x2, NT, DD, MM,
                                               mlp_b2, nullptr, x1);
    }
}

// round 3
// speedup vs baseline: 3.0607x; 3.0607x over previous
#include <cuda_runtime.h>
#include <math.h>
#include <stdint.h>

// ---------------- problem constants ----------------
#define BB 4
#define TT 4096
#define DD 1024
#define KK 128
#define HH 8
#define KER 4
#define MM 4096          // mlp hidden
#define C2K 256          // 2*K
#define NT (BB*TT)       // 16384 rows

// ---------------- scratch (static device, no allocs) ----------------
__device__ float g_xn[(size_t)NT*DD];      // LN1 out (tf32-rounded)
__device__ float g_beta0[(size_t)NT*C2K];
__device__ float g_pm[(size_t)NT*C2K];
__device__ float g_bR[(size_t)BB*KK*TT];
__device__ float g_bI[(size_t)BB*KK*TT];
__device__ float g_cR[(size_t)BB*KK*TT];
__device__ float g_cI[(size_t)BB*KK*TT];
__device__ float g_gate[(size_t)NT*DD];
__device__ float g_x1[(size_t)NT*DD];
__device__ float g_y[(size_t)NT*DD];       // LN2 out (tf32-rounded)
__device__ float g_h1[(size_t)NT*MM];      // mlp mid (tf32-rounded)
__device__ float g_eig_r[(size_t)NT*C2K];  // rounded copy of eig
__device__ float g_pe_r[(size_t)NT*C2K];   // rounded prev_eig
// rounded weights, packed
#define W_INPROJ  0
#define W_MEMPROJ (W_INPROJ + C2K*DD)
#define W_OUTPROJ (W_MEMPROJ + C2K*C2K)
#define W_GATE    (W_OUTPROJ + DD*C2K)
#define W_MLP1    (W_GATE + DD*DD)
#define W_MLP2    (W_MLP1 + (size_t)MM*DD)
#define W_TOTAL   (W_MLP2 + (size_t)DD*MM)
__device__ float g_wr[W_TOTAL];

__device__ __forceinline__ float sigmf(float x) { return 1.f / (1.f + __expf(-x)); }
__device__ __forceinline__ float rndtf32(float x) {
    uint32_t u; asm("cvt.rna.tf32.f32 %0, %1;" : "=r"(u) : "f"(x));
    return __uint_as_float(u);
}
__device__ __forceinline__ uint32_t smem_u32(const void* p) {
    uint32_t a;
    asm("{ .reg .u64 t; cvta.to.shared.u64 t, %1; cvt.u32.u64 %0, t; }" : "=r"(a) : "l"(p));
    return a;
}
__device__ __forceinline__ void cp16(uint32_t s, const void* g) {
    asm volatile("cp.async.cg.shared.global [%0], [%1], 16;" :: "r"(s), "l"(g));
}

// ============================ round-to-tf32 copy ============================
__global__ void round_tf32_kernel(const float* __restrict__ src, float* __restrict__ dst, int n4)
{
    int i = blockIdx.x * blockDim.x + threadIdx.x;
    if (i < n4) {
        float4 v = ((const float4*)src)[i];
        v.x = rndtf32(v.x); v.y = rndtf32(v.y); v.z = rndtf32(v.z); v.w = rndtf32(v.w);
        ((float4*)dst)[i] = v;
    }
}

// ============================ LayerNorm ============================
__global__ void ten_ln_kernel(const float* __restrict__ x,
                              const float* __restrict__ gw,
                              const float* __restrict__ bw,
                              float* __restrict__ y, int do_round)
{
    const int row = blockIdx.x;
    const int tid = threadIdx.x;
    const float4* xr = (const float4*)(x + (size_t)row * DD);
    float4 v = xr[tid];
    float s = v.x + v.y + v.z + v.w;
    float q = v.x*v.x + v.y*v.y + v.z*v.z + v.w*v.w;
    #pragma unroll
    for (int o = 16; o > 0; o >>= 1) {
        s += __shfl_xor_sync(0xffffffffu, s, o);
        q += __shfl_xor_sync(0xffffffffu, q, o);
    }
    __shared__ float ss[8], sq[8];
    const int w = tid >> 5, l = tid & 31;
    if (l == 0) { ss[w] = s; sq[w] = q; }
    __syncthreads();
    float st = 0.f, qt = 0.f;
    #pragma unroll
    for (int i = 0; i < 8; i++) { st += ss[i]; qt += sq[i]; }
    const float mean = st * (1.f / DD);
    const float var  = qt * (1.f / DD) - mean * mean;
    const float rstd = rsqrtf(var + 1e-5f);
    float4 g4 = ((const float4*)gw)[tid];
    float4 b4 = ((const float4*)bw)[tid];
    float4 o;
    o.x = (v.x - mean) * rstd * g4.x + b4.x;
    o.y = (v.y - mean) * rstd * g4.y + b4.y;
    o.z = (v.z - mean) * rstd * g4.z + b4.z;
    o.w = (v.w - mean) * rstd * g4.w + b4.w;
    if (do_round) { o.x = rndtf32(o.x); o.y = rndtf32(o.y); o.z = rndtf32(o.z); o.w = rndtf32(o.w); }
    ((float4*)(y + (size_t)row * DD))[tid] = o;
}

// ============================ tf32 mma.sync GEMM ============================
// C[M,N] = A[M,K] @ B[N,K]^T ; block tile 128x256, BK=32, 2-stage cp.async,
// 8 warps (2x4), warp tile 64x64 (4x8 m16n8k8), fused epilogues.
enum { EPI_NONE = 0, EPI_GATE = 1, EPI_SILU_BIAS = 2, EPI_BIAS_RES = 3 };

#define ASTR 36
#define SM_A (128*ASTR)
#define SM_B (256*ASTR)
#define GEMM_SMEM ((2*(SM_A+SM_B))*4)

template<int EPI>
__global__ void __launch_bounds__(256, 1)
mma_gemm(const float* __restrict__ A, const float* __restrict__ B, float* __restrict__ C,
         int M, int N, int K,
         const float* __restrict__ aux0, const float* __restrict__ aux1,
         const float* __restrict__ aux2)
{
    extern __shared__ float sm[];
    float* As = sm;                   // [2][128][36]
    float* Bs = sm + 2 * SM_A;        // [2][256][36]
    const uint32_t as_u = smem_u32(As);
    const uint32_t bs_u = smem_u32(Bs);
    const int tid = threadIdx.x;
    const int lane = tid & 31, wid = tid >> 5;
    const int wm = wid >> 2, wn = wid & 3;          // 2 x 4 warp grid
    const int m0 = blockIdx.y * 128, n0 = blockIdx.x * 256;
    const int nchunk = K >> 5;

    const float* Ag = A + (size_t)m0 * K;
    const float* Bg = B + (size_t)n0 * K;

    auto load_stage = [&](int s, int c) {
        const float* ac = Ag + c * 32;
        #pragma unroll
        for (int j = 0; j < 4; j++) {
            int idx = tid + j * 256; int r = idx >> 3; int u = (idx & 7) * 4;
            cp16(as_u + (uint32_t)(s * SM_A + r * ASTR + u) * 4, ac + (size_t)r * K + u);
        }
        const float* bc = Bg + c * 32;
        #pragma unroll
        for (int j = 0; j < 8; j++) {
            int idx = tid + j * 256; int r = idx >> 3; int u = (idx & 7) * 4;
            cp16(bs_u + (uint32_t)(s * SM_B + r * ASTR + u) * 4, bc + (size_t)r * K + u);
        }
        asm volatile("cp.async.commit_group;");
    };

    float acc[4][8][4];
    #pragma unroll
    for (int mi = 0; mi < 4; mi++)
        #pragma unroll
        for (int ni = 0; ni < 8; ni++)
            #pragma unroll
            for (int q = 0; q < 4; q++) acc[mi][ni][q] = 0.f;

    load_stage(0, 0);

    const int g = lane >> 2, t = lane & 3;
    for (int i = 0; i < nchunk; i++) {
        if (i + 1 < nchunk) {
            load_stage((i + 1) & 1, i + 1);
            asm volatile("cp.async.wait_group 1;" ::: "memory");
        } else {
            asm volatile("cp.async.wait_group 0;" ::: "memory");
        }
        __syncthreads();
        const float* a = As + (i & 1) * SM_A + (wm * 64 + g) * ASTR;
        const float* b = Bs + (i & 1) * SM_B + (wn * 64 + g) * ASTR;
        #pragma unroll
        for (int ks = 0; ks < 4; ks++) {
            uint32_t af[4][4], bf[8][2];
            #pragma unroll
            for (int mi = 0; mi < 4; mi++) {
                const float* ap = a + mi * 16 * ASTR + ks * 8 + t;
                af[mi][0] = __float_as_uint(ap[0]);
                af[mi][1] = __float_as_uint(ap[8 * ASTR]);
                af[mi][2] = __float_as_uint(ap[4]);
                af[mi][3] = __float_as_uint(ap[8 * ASTR + 4]);
            }
            #pragma unroll
            for (int ni = 0; ni < 8; ni++) {
                const float* bp = b + ni * 8 * ASTR + ks * 8 + t;
                bf[ni][0] = __float_as_uint(bp[0]);
                bf[ni][1] = __float_as_uint(bp[4]);
            }
            #pragma unroll
            for (int mi = 0; mi < 4; mi++)
                #pragma unroll
                for (int ni = 0; ni < 8; ni++)
                    asm volatile(
                        "mma.sync.aligned.m16n8k8.row.col.f32.tf32.tf32.f32 "
                        "{%0,%1,%2,%3}, {%4,%5,%6,%7}, {%8,%9}, {%0,%1,%2,%3};"
                        : "+f"(acc[mi][ni][0]), "+f"(acc[mi][ni][1]),
                          "+f"(acc[mi][ni][2]), "+f"(acc[mi][ni][3])
                        : "r"(af[mi][0]), "r"(af[mi][1]), "r"(af[mi][2]), "r"(af[mi][3]),
                          "r"(bf[ni][0]), "r"(bf[ni][1]));
        }
        __syncthreads();
    }

    // -------- epilogue: write C with fused ops --------
    #pragma unroll
    for (int mi = 0; mi < 4; mi++) {
        const int rbase = m0 + wm * 64 + mi * 16 + g;
        #pragma unroll
        for (int ni = 0; ni < 8; ni++) {
            const int cc = n0 + wn * 64 + ni * 8 + t * 2;
            #pragma unroll
            for (int half = 0; half < 2; half++) {
                const int r = rbase + half * 8;
                float v0 = acc[mi][ni][half * 2 + 0];
                float v1 = acc[mi][ni][half * 2 + 1];
                const size_t off = (size_t)r * N + cc;
                if (EPI == EPI_GATE) {
                    float2 gg = *(const float2*)(aux0 + off);
                    float2 gb = *(const float2*)(aux1 + cc);
                    float2 xr = *(const float2*)(aux2 + off);
                    v0 = xr.x + sigmf(gg.x + gb.x) * v0;
                    v1 = xr.y + sigmf(gg.y + gb.y) * v1;
                } else if (EPI == EPI_SILU_BIAS) {
                    float2 bb = *(const float2*)(aux0 + cc);
                    float t0 = v0 + bb.x, t1 = v1 + bb.y;
                    v0 = rndtf32(t0 * sigmf(t0));
                    v1 = rndtf32(t1 * sigmf(t1));
                } else if (EPI == EPI_BIAS_RES) {
                    float2 bb = *(const float2*)(aux0 + cc);
                    float2 xr = *(const float2*)(aux2 + off);
                    v0 = xr.x + v0 + bb.x;
                    v1 = xr.y + v1 + bb.y;
                }
                float2 o = {v0, v1};
                *(float2*)(C + off) = o;
            }
        }
    }
}

// ---------------- depthwise causal conv + bias + SiLU + mem inject ----------
__global__ void __launch_bounds__(256)
ten_conv_mem_kernel(const float* __restrict__ beta0,
                    const float* __restrict__ pm,
                    const float* __restrict__ conv_w,
                    const float* __restrict__ conv_b,
                    const float* __restrict__ mem_gate,
                    float* __restrict__ bR, float* __restrict__ bI)
{
    const int b   = blockIdx.z;
    const int cg0 = blockIdx.y * 32;
    const int t0  = blockIdx.x * 64;
    __shared__ float sb[67][33];
    __shared__ float sp[64][33];
    const int tid = threadIdx.x;

    for (int i = tid; i < 67 * 32; i += 256) {
        const int r = i >> 5, c = i & 31;
        const int t = t0 + r - 3;
        sb[r][c] = (t >= 0) ? beta0[((size_t)(b * TT + t)) * C2K + cg0 + c] : 0.f;
    }
    for (int i = tid; i < 64 * 32; i += 256) {
        const int r = i >> 5, c = i & 31;
        sp[r][c] = pm[((size_t)(b * TT + t0 + r)) * C2K + cg0 + c];
    }
    __syncthreads();

    const float mg = 1.f / (1.f + expf(-mem_gate[0]));
    const int cl = tid >> 3;
    const int tg = (tid & 7) * 8;
    const int cglob = cg0 + cl;
    const float w0 = conv_w[cglob * 4 + 0];
    const float w1 = conv_w[cglob * 4 + 1];
    const float w2 = conv_w[cglob * 4 + 2];
    const float w3 = conv_w[cglob * 4 + 3];
    const float cb = conv_b[cglob];
    const int k = cglob & (KK - 1);
    float* dst = ((cglob < KK) ? bR : bI) + ((size_t)(b * KK + k)) * TT + t0 + tg;
    #pragma unroll
    for (int j = 0; j < 8; j++) {
        const int r = tg + j;
        float v = sb[r][cl] * w0 + sb[r + 1][cl] * w1 + sb[r + 2][cl] * w2 + sb[r + 3][cl] * w3 + cb;
        v = v * (1.f / (1.f + __expf(-v)));
        v += mg * sp[r][cl];
        dst[j] = v;
    }
}

// ---------------- complex first-order recurrence scan -----------------------
__global__ void __launch_bounds__(256)
ten_scan_kernel(const float* __restrict__ bR, const float* __restrict__ bI,
                const float* __restrict__ log_decay, const float* __restrict__ freq,
                float* __restrict__ cR, float* __restrict__ cI)
{
    const int bk = blockIdx.x;
    const int k = bk & (KK - 1);
    const float mag = 1.f / (1.f + expf(-log_decay[k]));
    float snf, csf;
    sincosf(freq[k], &snf, &csf);
    const float lr = mag * csf, li = mag * snf;
    const int tid = threadIdx.x;
    const size_t base = (size_t)bk * TT + tid * 16;

    float xr[16], xi[16];
    #pragma unroll
    for (int v = 0; v < 4; v++) {
        float4 a = *(const float4*)(bR + base + v * 4);
        xr[v*4+0] = a.x; xr[v*4+1] = a.y; xr[v*4+2] = a.z; xr[v*4+3] = a.w;
        float4 c = *(const float4*)(bI + base + v * 4);
        xi[v*4+0] = c.x; xi[v*4+1] = c.y; xi[v*4+2] = c.z; xi[v*4+3] = c.w;
    }

    float cr = 0.f, ci = 0.f;
    #pragma unroll
    for (int j = 0; j < 16; j++) {
        float nr = fmaf(lr, cr, fmaf(-li, ci, xr[j]));
        float ni = fmaf(lr, ci, fmaf( li, cr, xi[j]));
        cr = nr; ci = ni;
        xr[j] = cr; xi[j] = ci;
    }

    float fr = lr, fi = li;
    #pragma unroll
    for (int s = 0; s < 4; s++) {
        float nr = fr * fr - fi * fi;
        float ni = 2.f * fr * fi;
        fr = nr; fi = ni;
    }

    __shared__ float sgr[256], sgi[256], sor[256], soi[256];
    sgr[tid] = fr; sgi[tid] = fi; sor[tid] = cr; soi[tid] = ci;
    __syncthreads();
    for (int d = 1; d < 256; d <<= 1) {
        float ngr = 0.f, ngi = 0.f, nor_ = 0.f, noi_ = 0.f;
        if (tid >= d) {
            const float pgr = sgr[tid - d], pgi = sgi[tid - d];
            const float por = sor[tid - d], poi = soi[tid - d];
            const float gr = sgr[tid], gi = sgi[tid];
            const float orr = sor[tid], oii = soi[tid];
            ngr  = gr * pgr - gi * pgi;
            ngi  = gr * pgi + gi * pgr;
            nor_ = gr * por - gi * poi + orr;
            noi_ = gr * poi + gi * por + oii;
        }
        __syncthreads();
        if (tid >= d) { sgr[tid] = ngr; sgi[tid] = ngi; sor[tid] = nor_; soi[tid] = noi_; }
        __syncthreads();
    }
    const float pr = (tid > 0) ? sor[tid - 1] : 0.f;
    const float pi = (tid > 0) ? soi[tid - 1] : 0.f;

    float lpr = lr, lpi = li;
    #pragma unroll
    for (int j = 0; j < 16; j++) {
        xr[j] = fmaf(lpr, pr, fmaf(-lpi, pi, xr[j]));
        xi[j] = fmaf(lpr, pi, fmaf( lpi, pr, xi[j]));
        float nr = lpr * lr - lpi * li;
        float ni = lpr * li + lpi * lr;
        lpr = nr; lpi = ni;
    }
    #pragma unroll
    for (int v = 0; v < 4; v++) {
        float4 a = {xr[v*4+0], xr[v*4+1], xr[v*4+2], xr[v*4+3]};
        *(float4*)(cR + base + v * 4) = a;
        float4 c = {xi[v*4+0], xi[v*4+1], xi[v*4+2], xi[v*4+3]};
        *(float4*)(cI + base + v * 4) = c;
    }
}

// ---------------- coupling + transpose -> eig (exact) + rounded copy --------
__global__ void __launch_bounds__(256)
ten_coupling_kernel(const float* __restrict__ cR, const float* __restrict__ cI,
                    const float* __restrict__ coupling,
                    float* __restrict__ eig, float* __restrict__ eig_r)
{
    const int b = blockIdx.z, h = blockIdx.y;
    const int t0 = blockIdx.x * 256;
    const int tid = threadIdx.x;
    __shared__ float sr[16][256];
    __shared__ float si[16][256];
    __shared__ float w[16][16];
    w[tid >> 4][tid & 15] = coupling[h * 256 + tid];
    #pragma unroll
    for (int kk = 0; kk < 16; kk++) {
        const size_t src = ((size_t)(b * KK + h * 16 + kk)) * TT + t0 + tid;
        sr[kk][tid] = cR[src];
        si[kk][tid] = cI[src];
    }
    __syncthreads();
    float orr[16], oii[16];
    #pragma unroll
    for (int j = 0; j < 16; j++) { orr[j] = 0.f; oii[j] = 0.f; }
    #pragma unroll
    for (int kk = 0; kk < 16; kk++) {
        const float vr = sr[kk][tid];
        const float vi = si[kk][tid];
        #pragma unroll
        for (int j = 0; j < 16; j++) {
            orr[j] = fmaf(w[j][kk], vr, orr[j]);
            oii[j] = fmaf(w[j][kk], vi, oii[j]);
        }
    }
    const size_t dst = ((size_t)(b * TT + t0 + tid)) * C2K + h * 16;
    #pragma unroll
    for (int j = 0; j < 16; j += 4) {
        float4 v = {orr[j], orr[j+1], orr[j+2], orr[j+3]};
        *(float4*)(eig + dst + j) = v;
        float4 u = {oii[j], oii[j+1], oii[j+2], oii[j+3]};
        *(float4*)(eig + dst + KK + j) = u;
        float4 vr_ = {rndtf32(orr[j]), rndtf32(orr[j+1]), rndtf32(orr[j+2]), rndtf32(orr[j+3])};
        *(float4*)(eig_r + dst + j) = vr_;
        float4 ur_ = {rndtf32(oii[j]), rndtf32(oii[j+1]), rndtf32(oii[j+2]), rndtf32(oii[j+3])};
        *(float4*)(eig_r + dst + KK + j) = ur_;
    }
}

// ---------------- launch -----------------------------------------------------
extern "C" void kernel_launch(void* const* d_in, const int* in_sizes, int n_in,
                              void* d_out, int out_size)
{
    const float* x          = (const float*)d_in[0];
    const float* prev_eig   = (const float*)d_in[1];
    const float* in_proj_w  = (const float*)d_in[2];
    const float* conv_w     = (const float*)d_in[3];
    const float* conv_b     = (const float*)d_in[4];
    const float* mem_gate   = (const float*)d_in[5];
    const float* mem_proj_w = (const float*)d_in[6];
    const float* log_decay  = (const float*)d_in[7];
    const float* frequency  = (const float*)d_in[8];
    const float* coupling   = (const float*)d_in[9];
    const float* out_proj_w = (const float*)d_in[10];
    const float* gate_w     = (const float*)d_in[11];
    const float* gate_b     = (const float*)d_in[12];
    const float* mlp_w1     = (const float*)d_in[13];
    const float* mlp_b1     = (const float*)d_in[14];
    const float* mlp_w2     = (const float*)d_in[15];
    const float* mlp_b2     = (const float*)d_in[16];
    const float* n1_g       = (const float*)d_in[17];
    const float* n1_b       = (const float*)d_in[18];
    const float* n2_g       = (const float*)d_in[19];
    const float* n2_b       = (const float*)d_in[20];

    float* out_x2  = (float*)d_out;
    float* out_eig = out_x2 + (size_t)NT * DD;

    float *xn, *beta0, *pm, *bRp, *bIp, *cRp, *cIp, *gate, *x1, *y, *h1, *eig_r, *pe_r, *wr;
    cudaGetSymbolAddress((void**)&xn,    g_xn);
    cudaGetSymbolAddress((void**)&beta0, g_beta0);
    cudaGetSymbolAddress((void**)&pm,    g_pm);
    cudaGetSymbolAddress((void**)&bRp,   g_bR);
    cudaGetSymbolAddress((void**)&bIp,   g_bI);
    cudaGetSymbolAddress((void**)&cRp,   g_cR);
    cudaGetSymbolAddress((void**)&cIp,   g_cI);
    cudaGetSymbolAddress((void**)&gate,  g_gate);
    cudaGetSymbolAddress((void**)&x1,    g_x1);
    cudaGetSymbolAddress((void**)&y,     g_y);
    cudaGetSymbolAddress((void**)&h1,    g_h1);
    cudaGetSymbolAddress((void**)&eig_r, g_eig_r);
    cudaGetSymbolAddress((void**)&pe_r,  g_pe_r);
    cudaGetSymbolAddress((void**)&wr,    g_wr);

    cudaFuncSetAttribute(mma_gemm<EPI_NONE>,      cudaFuncAttributeMaxDynamicSharedMemorySize, GEMM_SMEM);
    cudaFuncSetAttribute(mma_gemm<EPI_GATE>,      cudaFuncAttributeMaxDynamicSharedMemorySize, GEMM_SMEM);
    cudaFuncSetAttribute(mma_gemm<EPI_SILU_BIAS>, cudaFuncAttributeMaxDynamicSharedMemorySize, GEMM_SMEM);
    cudaFuncSetAttribute(mma_gemm<EPI_BIAS_RES>,  cudaFuncAttributeMaxDynamicSharedMemorySize, GEMM_SMEM);

    auto rc = [&](const float* s, float* d, size_t n) {
        int n4 = (int)(n / 4);
        round_tf32_kernel<<<(n4 + 255) / 256, 256>>>(s, d, n4);
    };
    // round weights + prev_eig to nearest-tf32 (kills HW truncation bias)
    rc(in_proj_w,  wr + W_INPROJ,  (size_t)C2K * DD);
    rc(mem_proj_w, wr + W_MEMPROJ, (size_t)C2K * C2K);
    rc(out_proj_w, wr + W_OUTPROJ, (size_t)DD * C2K);
    rc(gate_w,     wr + W_GATE,    (size_t)DD * DD);
    rc(mlp_w1,     wr + W_MLP1,    (size_t)MM * DD);
    rc(mlp_w2,     wr + W_MLP2,    (size_t)DD * MM);
    rc(prev_eig,   pe_r,           (size_t)NT * C2K);

    // 1) LN1 (rounded output)
    ten_ln_kernel<<<NT, 256>>>(x, n1_g, n1_b, xn, 1);

    // 2) beta0 = xn @ in_proj_w^T   [16384,256]
    mma_gemm<EPI_NONE><<<dim3(C2K/256, NT/128), 256, GEMM_SMEM>>>(
        xn, wr + W_INPROJ, beta0, NT, C2K, DD, nullptr, nullptr, nullptr);
    // 3) pm = prev_eig @ mem_proj_w^T  [16384,256]
    mma_gemm<EPI_NONE><<<dim3(C2K/256, NT/128), 256, GEMM_SMEM>>>(
        pe_r, wr + W_MEMPROJ, pm, NT, C2K, C2K, nullptr, nullptr, nullptr);

    // 4) conv + SiLU + mem inject
    ten_conv_mem_kernel<<<dim3(TT/64, C2K/32, BB), 256>>>(
        beta0, pm, conv_w, conv_b, mem_gate, bRp, bIp);
    // 5) recurrence scan
    ten_scan_kernel<<<BB * KK, 256>>>(bRp, bIp, log_decay, frequency, cRp, cIp);
    // 6) coupling -> eig (exact) + rounded copy
    ten_coupling_kernel<<<dim3(TT/256, HH, BB), 256>>>(cRp, cIp, coupling, out_eig, eig_r);

    // 7) gate pre-activation   [16384,1024]
    mma_gemm<EPI_NONE><<<dim3(DD/256, NT/128), 256, GEMM_SMEM>>>(
        xn, wr + W_GATE, gate, NT, DD, DD, nullptr, nullptr, nullptr);
    // 8) x1 = x + sigmoid(gate+gate_b) * (eig @ out_proj^T)
    mma_gemm<EPI_GATE><<<dim3(DD/256, NT/128), 256, GEMM_SMEM>>>(
        eig_r, wr + W_OUTPROJ, x1, NT, DD, C2K, gate, gate_b, x);

    // 9) LN2 (rounded output)
    ten_ln_kernel<<<NT, 256>>>(x1, n2_g, n2_b, y, 1);

    // 10) h1 = silu(y @ w1^T + b1) (rounded output)  [16384,4096]
    mma_gemm<EPI_SILU_BIAS><<<dim3(MM/256, NT/128), 256, GEMM_SMEM>>>(
        y, wr + W_MLP1, h1, NT, MM, DD, mlp_b1, nullptr, nullptr);
    // 11) x2 = x1 + h1 @ w2^T + b2  [16384,1024]
    mma_gemm<EPI_BIAS_RES><<<dim3(DD/256, NT/128), 256, GEMM_SMEM>>>(
        h1, wr + W_MLP2, out_x2, NT, DD, MM, mlp_b2, nullptr, x1);
}

// round 4
// speedup vs baseline: 5.3749x; 1.7561x over previous
#include <cuda_runtime.h>
#include <cuda_fp16.h>
#include <math.h>
#include <stdint.h>

// ---------------- problem constants ----------------
#define BB 4
#define TT 4096
#define DD 1024
#define KK 128
#define HH 8
#define KER 4
#define MM 4096          // mlp hidden
#define C2K 256          // 2*K
#define NT (BB*TT)       // 16384 rows

// ---------------- scratch (static device, no allocs) ----------------
__device__ __half g_xn_h[(size_t)NT*DD];     // LN1 out fp16
__device__ __half g_y_h[(size_t)NT*DD];      // LN2 out fp16
__device__ __half g_h1_h[(size_t)NT*MM];     // mlp mid fp16
__device__ __half g_eig_h[(size_t)NT*C2K];   // fp16 copy of eig
__device__ __half g_pe_h[(size_t)NT*C2K];    // fp16 prev_eig
__device__ float  g_beta0[(size_t)NT*C2K];
__device__ float  g_pm[(size_t)NT*C2K];
__device__ float  g_bR[(size_t)BB*KK*TT];
__device__ float  g_bI[(size_t)BB*KK*TT];
__device__ float  g_cR[(size_t)BB*KK*TT];
__device__ float  g_cI[(size_t)BB*KK*TT];
__device__ float  g_sig[(size_t)NT*DD];
__device__ float  g_x1[(size_t)NT*DD];
// fp16 weights, packed
#define W_INPROJ  0
#define W_MEMPROJ (W_INPROJ + C2K*DD)
#define W_OUTPROJ (W_MEMPROJ + C2K*C2K)
#define W_GATE    (W_OUTPROJ + DD*C2K)
#define W_MLP1    (W_GATE + DD*DD)
#define W_MLP2    (W_MLP1 + (size_t)MM*DD)
#define W_TOTAL   (W_MLP2 + (size_t)DD*MM)
__device__ __half g_wh[W_TOTAL];

__device__ __forceinline__ float sigmf(float x) { return 1.f / (1.f + __expf(-x)); }
__device__ __forceinline__ uint32_t smem_u32(const void* p) {
    uint32_t a;
    asm("{ .reg .u64 t; cvta.to.shared.u64 t, %1; cvt.u32.u64 %0, t; }" : "=r"(a) : "l"(p));
    return a;
}
__device__ __forceinline__ void cp16(uint32_t s, const void* g) {
    asm volatile("cp.async.cg.shared.global [%0], [%1], 16;" :: "r"(s), "l"(g));
}
__device__ __forceinline__ uint32_t h2u(__half2 h) { return *(uint32_t*)&h; }

// ============================ fp32 -> fp16 convert ============================
__global__ void f32_to_f16_kernel(const float* __restrict__ s, __half* __restrict__ d, int n8)
{
    int i = blockIdx.x * blockDim.x + threadIdx.x;
    if (i < n8) {
        const float4* s4 = (const float4*)s + 2 * (size_t)i;
        float4 a = s4[0], b = s4[1];
        __half2 h0 = __floats2half2_rn(a.x, a.y);
        __half2 h1 = __floats2half2_rn(a.z, a.w);
        __half2 h2 = __floats2half2_rn(b.x, b.y);
        __half2 h3 = __floats2half2_rn(b.z, b.w);
        uint4 o = {h2u(h0), h2u(h1), h2u(h2), h2u(h3)};
        ((uint4*)d)[i] = o;
    }
}

// ============================ LayerNorm -> fp16 out ============================
__global__ void ten_ln_kernel(const float* __restrict__ x,
                              const float* __restrict__ gw,
                              const float* __restrict__ bw,
                              __half* __restrict__ yh)
{
    const int row = blockIdx.x;
    const int tid = threadIdx.x;
    const float4* xr = (const float4*)(x + (size_t)row * DD);
    float4 v = xr[tid];
    float s = v.x + v.y + v.z + v.w;
    float q = v.x*v.x + v.y*v.y + v.z*v.z + v.w*v.w;
    #pragma unroll
    for (int o = 16; o > 0; o >>= 1) {
        s += __shfl_xor_sync(0xffffffffu, s, o);
        q += __shfl_xor_sync(0xffffffffu, q, o);
    }
    __shared__ float ss[8], sq[8];
    const int w = tid >> 5, l = tid & 31;
    if (l == 0) { ss[w] = s; sq[w] = q; }
    __syncthreads();
    float st = 0.f, qt = 0.f;
    #pragma unroll
    for (int i = 0; i < 8; i++) { st += ss[i]; qt += sq[i]; }
    const float mean = st * (1.f / DD);
    const float var  = qt * (1.f / DD) - mean * mean;
    const float rstd = rsqrtf(var + 1e-5f);
    float4 g4 = ((const float4*)gw)[tid];
    float4 b4 = ((const float4*)bw)[tid];
    float ox = (v.x - mean) * rstd * g4.x + b4.x;
    float oy = (v.y - mean) * rstd * g4.y + b4.y;
    float oz = (v.z - mean) * rstd * g4.z + b4.z;
    float ow = (v.w - mean) * rstd * g4.w + b4.w;
    __half2 o0 = __floats2half2_rn(ox, oy);
    __half2 o1 = __floats2half2_rn(oz, ow);
    uint2 ov = {h2u(o0), h2u(o1)};
    ((uint2*)(yh + (size_t)row * DD))[tid] = ov;
}

// ============================ fp16 mma.sync GEMM ============================
// C[M,N] = A[M,K] @ B[N,K]^T ; block 128x256, BK=64 halves, 3-stage cp.async,
// 8 warps (2x4), warp tile 64x64 (4x8 m16n8k16), fused epilogues.
enum { EPI_NONE = 0, EPI_SIG = 1, EPI_GATE = 2, EPI_SILU_H = 3, EPI_BIAS_RES = 4 };

#define ASTR 36                    // b32 per SMEM row (32 data + 4 pad)
#define A_B32 (128*ASTR)           // 4608
#define B_B32 (256*ASTR)           // 9216
#define ST_B32 (A_B32 + B_B32)     // 13824
#define GEMM_SMEM (3*ST_B32*4)     // 165888 B

template<int EPI>
__global__ void __launch_bounds__(256, 1)
mma_gemm(const __half* __restrict__ A, const __half* __restrict__ B, void* Cv,
         int M, int N, int K,
         const float* __restrict__ aux0, const float* __restrict__ aux1,
         const float* __restrict__ aux2)
{
    extern __shared__ uint32_t smu[];
    const uint32_t sm_base = smem_u32(smu);
    const int tid = threadIdx.x;
    const int lane = tid & 31, wid = tid >> 5;
    const int wm = wid >> 2, wn = wid & 3;          // 2 x 4 warp grid
    const int m0 = blockIdx.y * 128, n0 = blockIdx.x * 256;
    const int nchunk = K >> 6;
    const int g = lane >> 2, t = lane & 3;

    const __half* Ag = A + (size_t)m0 * K;
    const __half* Bg = B + (size_t)n0 * K;

    auto load_stage = [&](int s, int c) {
        const uint32_t sb = sm_base + (uint32_t)(s * ST_B32) * 4;
        const __half* ac = Ag + (size_t)c * 64;
        #pragma unroll
        for (int j = 0; j < 4; j++) {
            int idx = tid + j * 256; int r = idx >> 3; int u = idx & 7;
            cp16(sb + (uint32_t)(r * ASTR + u * 4) * 4, ac + (size_t)r * K + u * 8);
        }
        const __half* bc = Bg + (size_t)c * 64;
        #pragma unroll
        for (int j = 0; j < 8; j++) {
            int idx = tid + j * 256; int r = idx >> 3; int u = idx & 7;
            cp16(sb + (uint32_t)(A_B32 + r * ASTR + u * 4) * 4, bc + (size_t)r * K + u * 8);
        }
        asm volatile("cp.async.commit_group;");
    };

    float acc[4][8][4];
    #pragma unroll
    for (int mi = 0; mi < 4; mi++)
        #pragma unroll
        for (int ni = 0; ni < 8; ni++)
            #pragma unroll
            for (int q = 0; q < 4; q++) acc[mi][ni][q] = 0.f;

    load_stage(0, 0);
    if (1 < nchunk) load_stage(1, 1);

    int stage = 0;
    for (int i = 0; i < nchunk; i++) {
        if (i == nchunk - 1) asm volatile("cp.async.wait_group 0;" ::: "memory");
        else                 asm volatile("cp.async.wait_group 1;" ::: "memory");
        __syncthreads();
        if (i + 2 < nchunk) {
            int ns = stage + 2; if (ns >= 3) ns -= 3;
            load_stage(ns, i + 2);
        }
        const uint32_t* st = smu + stage * ST_B32;
        const uint32_t* ab = st + (wm * 64 + g) * ASTR;
        const uint32_t* bb = st + A_B32 + (wn * 64 + g) * ASTR;
        #pragma unroll
        for (int ks = 0; ks < 4; ks++) {
            const int ko = ks * 8;
            uint32_t af[4][4], bf[8][2];
            #pragma unroll
            for (int mi = 0; mi < 4; mi++) {
                const uint32_t* ap = ab + mi * (16 * ASTR) + ko + t;
                af[mi][0] = ap[0];
                af[mi][1] = ap[8 * ASTR];
                af[mi][2] = ap[4];
                af[mi][3] = ap[8 * ASTR + 4];
            }
            #pragma unroll
            for (int ni = 0; ni < 8; ni++) {
                const uint32_t* bp = bb + ni * (8 * ASTR) + ko + t;
                bf[ni][0] = bp[0];
                bf[ni][1] = bp[4];
            }
            #pragma unroll
            for (int mi = 0; mi < 4; mi++)
                #pragma unroll
                for (int ni = 0; ni < 8; ni++)
                    asm volatile(
                        "mma.sync.aligned.m16n8k16.row.col.f32.f16.f16.f32 "
                        "{%0,%1,%2,%3}, {%4,%5,%6,%7}, {%8,%9}, {%0,%1,%2,%3};"
                        : "+f"(acc[mi][ni][0]), "+f"(acc[mi][ni][1]),
                          "+f"(acc[mi][ni][2]), "+f"(acc[mi][ni][3])
                        : "r"(af[mi][0]), "r"(af[mi][1]), "r"(af[mi][2]), "r"(af[mi][3]),
                          "r"(bf[ni][0]), "r"(bf[ni][1]));
        }
        if (++stage == 3) stage = 0;
    }

    // -------- epilogue --------
    float* Cf = (float*)Cv;
    __half* Ch = (__half*)Cv;
    #pragma unroll
    for (int mi = 0; mi < 4; mi++) {
        const int rbase = m0 + wm * 64 + mi * 16 + g;
        #pragma unroll
        for (int ni = 0; ni < 8; ni++) {
            const int cc = n0 + wn * 64 + ni * 8 + t * 2;
            #pragma unroll
            for (int half_ = 0; half_ < 2; half_++) {
                const int r = rbase + half_ * 8;
                float v0 = acc[mi][ni][half_ * 2 + 0];
                float v1 = acc[mi][ni][half_ * 2 + 1];
                const size_t off = (size_t)r * N + cc;
                if (EPI == EPI_NONE) {
                    float2 o = {v0, v1};
                    *(float2*)(Cf + off) = o;
                } else if (EPI == EPI_SIG) {
                    float2 gb = *(const float2*)(aux0 + cc);
                    float2 o = {sigmf(v0 + gb.x), sigmf(v1 + gb.y)};
                    *(float2*)(Cf + off) = o;
                } else if (EPI == EPI_GATE) {
                    float2 sg = *(const float2*)(aux0 + off);
                    float2 xr = *(const float2*)(aux2 + off);
                    float2 o = {xr.x + sg.x * v0, xr.y + sg.y * v1};
                    *(float2*)(Cf + off) = o;
                } else if (EPI == EPI_SILU_H) {
                    float2 bb = *(const float2*)(aux0 + cc);
                    float t0 = v0 + bb.x, t1 = v1 + bb.y;
                    __half2 o = __floats2half2_rn(t0 * sigmf(t0), t1 * sigmf(t1));
                    *(uint32_t*)(Ch + off) = h2u(o);
                } else if (EPI == EPI_BIAS_RES) {
                    float2 bb = *(const float2*)(aux0 + cc);
                    float2 xr = *(const float2*)(aux2 + off);
                    float2 o = {xr.x + v0 + bb.x, xr.y + v1 + bb.y};
                    *(float2*)(Cf + off) = o;
                }
            }
        }
    }
}

// ---------------- depthwise causal conv + bias + SiLU + mem inject ----------
__global__ void __launch_bounds__(256)
ten_conv_mem_kernel(const float* __restrict__ beta0,
                    const float* __restrict__ pm,
                    const float* __restrict__ conv_w,
                    const float* __restrict__ conv_b,
                    const float* __restrict__ mem_gate,
                    float* __restrict__ bR, float* __restrict__ bI)
{
    const int b   = blockIdx.z;
    const int cg0 = blockIdx.y * 32;
    const int t0  = blockIdx.x * 64;
    __shared__ float sb[67][33];
    __shared__ float sp[64][33];
    const int tid = threadIdx.x;

    for (int i = tid; i < 67 * 32; i += 256) {
        const int r = i >> 5, c = i & 31;
        const int t = t0 + r - 3;
        sb[r][c] = (t >= 0) ? beta0[((size_t)(b * TT + t)) * C2K + cg0 + c] : 0.f;
    }
    for (int i = tid; i < 64 * 32; i += 256) {
        const int r = i >> 5, c = i & 31;
        sp[r][c] = pm[((size_t)(b * TT + t0 + r)) * C2K + cg0 + c];
    }
    __syncthreads();

    const float mg = 1.f / (1.f + expf(-mem_gate[0]));
    const int cl = tid >> 3;
    const int tg = (tid & 7) * 8;
    const int cglob = cg0 + cl;
    const float w0 = conv_w[cglob * 4 + 0];
    const float w1 = conv_w[cglob * 4 + 1];
    const float w2 = conv_w[cglob * 4 + 2];
    const float w3 = conv_w[cglob * 4 + 3];
    const float cb = conv_b[cglob];
    const int k = cglob & (KK - 1);
    float* dst = ((cglob < KK) ? bR : bI) + ((size_t)(b * KK + k)) * TT + t0 + tg;
    #pragma unroll
    for (int j = 0; j < 8; j++) {
        const int r = tg + j;
        float v = sb[r][cl] * w0 + sb[r + 1][cl] * w1 + sb[r + 2][cl] * w2 + sb[r + 3][cl] * w3 + cb;
        v = v * (1.f / (1.f + __expf(-v)));
        v += mg * sp[r][cl];
        dst[j] = v;
    }
}

// ---------------- complex first-order recurrence scan -----------------------
__global__ void __launch_bounds__(256)
ten_scan_kernel(const float* __restrict__ bR, const float* __restrict__ bI,
                const float* __restrict__ log_decay, const float* __restrict__ freq,
                float* __restrict__ cR, float* __restrict__ cI)
{
    const int bk = blockIdx.x;
    const int k = bk & (KK - 1);
    const float mag = 1.f / (1.f + expf(-log_decay[k]));
    float snf, csf;
    sincosf(freq[k], &snf, &csf);
    const float lr = mag * csf, li = mag * snf;
    const int tid = threadIdx.x;
    const size_t base = (size_t)bk * TT + tid * 16;

    float xr[16], xi[16];
    #pragma unroll
    for (int v = 0; v < 4; v++) {
        float4 a = *(const float4*)(bR + base + v * 4);
        xr[v*4+0] = a.x; xr[v*4+1] = a.y; xr[v*4+2] = a.z; xr[v*4+3] = a.w;
        float4 c = *(const float4*)(bI + base + v * 4);
        xi[v*4+0] = c.x; xi[v*4+1] = c.y; xi[v*4+2] = c.z; xi[v*4+3] = c.w;
    }

    float cr = 0.f, ci = 0.f;
    #pragma unroll
    for (int j = 0; j < 16; j++) {
        float nr = fmaf(lr, cr, fmaf(-li, ci, xr[j]));
        float ni = fmaf(lr, ci, fmaf( li, cr, xi[j]));
        cr = nr; ci = ni;
        xr[j] = cr; xi[j] = ci;
    }

    float fr = lr, fi = li;
    #pragma unroll
    for (int s = 0; s < 4; s++) {
        float nr = fr * fr - fi * fi;
        float ni = 2.f * fr * fi;
        fr = nr; fi = ni;
    }

    __shared__ float sgr[256], sgi[256], sor[256], soi[256];
    sgr[tid] = fr; sgi[tid] = fi; sor[tid] = cr; soi[tid] = ci;
    __syncthreads();
    for (int d = 1; d < 256; d <<= 1) {
        float ngr = 0.f, ngi = 0.f, nor_ = 0.f, noi_ = 0.f;
        if (tid >= d) {
            const float pgr = sgr[tid - d], pgi = sgi[tid - d];
            const float por = sor[tid - d], poi = soi[tid - d];
            const float gr = sgr[tid], gi = sgi[tid];
            const float orr = sor[tid], oii = soi[tid];
            ngr  = gr * pgr - gi * pgi;
            ngi  = gr * pgi + gi * pgr;
            nor_ = gr * por - gi * poi + orr;
            noi_ = gr * poi + gi * por + oii;
        }
        __syncthreads();
        if (tid >= d) { sgr[tid] = ngr; sgi[tid] = ngi; sor[tid] = nor_; soi[tid] = noi_; }
        __syncthreads();
    }
    const float pr = (tid > 0) ? sor[tid - 1] : 0.f;
    const float pi = (tid > 0) ? soi[tid - 1] : 0.f;

    float lpr = lr, lpi = li;
    #pragma unroll
    for (int j = 0; j < 16; j++) {
        xr[j] = fmaf(lpr, pr, fmaf(-lpi, pi, xr[j]));
        xi[j] = fmaf(lpr, pi, fmaf( lpi, pr, xi[j]));
        float nr = lpr * lr - lpi * li;
        float ni = lpr * li + lpi * lr;
        lpr = nr; lpi = ni;
    }
    #pragma unroll
    for (int v = 0; v < 4; v++) {
        float4 a = {xr[v*4+0], xr[v*4+1], xr[v*4+2], xr[v*4+3]};
        *(float4*)(cR + base + v * 4) = a;
        float4 c = {xi[v*4+0], xi[v*4+1], xi[v*4+2], xi[v*4+3]};
        *(float4*)(cI + base + v * 4) = c;
    }
}

// ---------------- coupling + transpose -> eig fp32 (output) + fp16 copy -----
__global__ void __launch_bounds__(256)
ten_coupling_kernel(const float* __restrict__ cR, const float* __restrict__ cI,
                    const float* __restrict__ coupling,
                    float* __restrict__ eig, __half* __restrict__ eig_h)
{
    const int b = blockIdx.z, h = blockIdx.y;
    const int t0 = blockIdx.x * 256;
    const int tid = threadIdx.x;
    __shared__ float sr[16][256];
    __shared__ float si[16][256];
    __shared__ float w[16][16];
    w[tid >> 4][tid & 15] = coupling[h * 256 + tid];
    #pragma unroll
    for (int kk = 0; kk < 16; kk++) {
        const size_t src = ((size_t)(b * KK + h * 16 + kk)) * TT + t0 + tid;
        sr[kk][tid] = cR[src];
        si[kk][tid] = cI[src];
    }
    __syncthreads();
    float orr[16], oii[16];
    #pragma unroll
    for (int j = 0; j < 16; j++) { orr[j] = 0.f; oii[j] = 0.f; }
    #pragma unroll
    for (int kk = 0; kk < 16; kk++) {
        const float vr = sr[kk][tid];
        const float vi = si[kk][tid];
        #pragma unroll
        for (int j = 0; j < 16; j++) {
            orr[j] = fmaf(w[j][kk], vr, orr[j]);
            oii[j] = fmaf(w[j][kk], vi, oii[j]);
        }
    }
    const size_t dst = ((size_t)(b * TT + t0 + tid)) * C2K + h * 16;
    #pragma unroll
    for (int j = 0; j < 16; j += 4) {
        float4 v = {orr[j], orr[j+1], orr[j+2], orr[j+3]};
        *(float4*)(eig + dst + j) = v;
        float4 u = {oii[j], oii[j+1], oii[j+2], oii[j+3]};
        *(float4*)(eig + dst + KK + j) = u;
        __half2 vh0 = __floats2half2_rn(orr[j], orr[j+1]);
        __half2 vh1 = __floats2half2_rn(orr[j+2], orr[j+3]);
        uint2 vv = {h2u(vh0), h2u(vh1)};
        *(uint2*)(eig_h + dst + j) = vv;
        __half2 uh0 = __floats2half2_rn(oii[j], oii[j+1]);
        __half2 uh1 = __floats2half2_rn(oii[j+2], oii[j+3]);
        uint2 uu = {h2u(uh0), h2u(uh1)};
        *(uint2*)(eig_h + dst + KK + j) = uu;
    }
}

// ---------------- launch -----------------------------------------------------
extern "C" void kernel_launch(void* const* d_in, const int* in_sizes, int n_in,
                              void* d_out, int out_size)
{
    const float* x          = (const float*)d_in[0];
    const float* prev_eig   = (const float*)d_in[1];
    const float* in_proj_w  = (const float*)d_in[2];
    const float* conv_w     = (const float*)d_in[3];
    const float* conv_b     = (const float*)d_in[4];
    const float* mem_gate   = (const float*)d_in[5];
    const float* mem_proj_w = (const float*)d_in[6];
    const float* log_decay  = (const float*)d_in[7];
    const float* frequency  = (const float*)d_in[8];
    const float* coupling   = (const float*)d_in[9];
    const float* out_proj_w = (const float*)d_in[10];
    const float* gate_w     = (const float*)d_in[11];
    const float* gate_b     = (const float*)d_in[12];
    const float* mlp_w1     = (const float*)d_in[13];
    const float* mlp_b1     = (const float*)d_in[14];
    const float* mlp_w2     = (const float*)d_in[15];
    const float* mlp_b2     = (const float*)d_in[16];
    const float* n1_g       = (const float*)d_in[17];
    const float* n1_b       = (const float*)d_in[18];
    const float* n2_g       = (const float*)d_in[19];
    const float* n2_b       = (const float*)d_in[20];

    float* out_x2  = (float*)d_out;
    float* out_eig = out_x2 + (size_t)NT * DD;

    __half *xn_h, *y_h, *h1_h, *eig_h, *pe_h, *wh;
    float *beta0, *pm, *bRp, *bIp, *cRp, *cIp, *sig, *x1;
    cudaGetSymbolAddress((void**)&xn_h,  g_xn_h);
    cudaGetSymbolAddress((void**)&y_h,   g_y_h);
    cudaGetSymbolAddress((void**)&h1_h,  g_h1_h);
    cudaGetSymbolAddress((void**)&eig_h, g_eig_h);
    cudaGetSymbolAddress((void**)&pe_h,  g_pe_h);
    cudaGetSymbolAddress((void**)&wh,    g_wh);
    cudaGetSymbolAddress((void**)&beta0, g_beta0);
    cudaGetSymbolAddress((void**)&pm,    g_pm);
    cudaGetSymbolAddress((void**)&bRp,   g_bR);
    cudaGetSymbolAddress((void**)&bIp,   g_bI);
    cudaGetSymbolAddress((void**)&cRp,   g_cR);
    cudaGetSymbolAddress((void**)&cIp,   g_cI);
    cudaGetSymbolAddress((void**)&sig,   g_sig);
    cudaGetSymbolAddress((void**)&x1,    g_x1);

    cudaFuncSetAttribute(mma_gemm<EPI_NONE>,     cudaFuncAttributeMaxDynamicSharedMemorySize, GEMM_SMEM);
    cudaFuncSetAttribute(mma_gemm<EPI_SIG>,      cudaFuncAttributeMaxDynamicSharedMemorySize, GEMM_SMEM);
    cudaFuncSetAttribute(mma_gemm<EPI_GATE>,     cudaFuncAttributeMaxDynamicSharedMemorySize, GEMM_SMEM);
    cudaFuncSetAttribute(mma_gemm<EPI_SILU_H>,   cudaFuncAttributeMaxDynamicSharedMemorySize, GEMM_SMEM);
    cudaFuncSetAttribute(mma_gemm<EPI_BIAS_RES>, cudaFuncAttributeMaxDynamicSharedMemorySize, GEMM_SMEM);

    auto cvt = [&](const float* s, __half* d, size_t n) {
        int n8 = (int)(n / 8);
        f32_to_f16_kernel<<<(n8 + 255) / 256, 256>>>(s, d, n8);
    };
    cvt(in_proj_w,  wh + W_INPROJ,  (size_t)C2K * DD);
    cvt(mem_proj_w, wh + W_MEMPROJ, (size_t)C2K * C2K);
    cvt(out_proj_w, wh + W_OUTPROJ, (size_t)DD * C2K);
    cvt(gate_w,     wh + W_GATE,    (size_t)DD * DD);
    cvt(mlp_w1,     wh + W_MLP1,    (size_t)MM * DD);
    cvt(mlp_w2,     wh + W_MLP2,    (size_t)DD * MM);
    cvt(prev_eig,   pe_h,           (size_t)NT * C2K);

    // 1) LN1 -> fp16
    ten_ln_kernel<<<NT, 256>>>(x, n1_g, n1_b, xn_h);

    // 2) beta0 = xn @ in_proj_w^T   [16384,256] fp32 out
    mma_gemm<EPI_NONE><<<dim3(C2K/256, NT/128), 256, GEMM_SMEM>>>(
        xn_h, wh + W_INPROJ, beta0, NT, C2K, DD, nullptr, nullptr, nullptr);
    // 3) pm = prev_eig @ mem_proj_w^T  [16384,256]
    mma_gemm<EPI_NONE><<<dim3(C2K/256, NT/128), 256, GEMM_SMEM>>>(
        pe_h, wh + W_MEMPROJ, pm, NT, C2K, C2K, nullptr, nullptr, nullptr);
    // 4) gate sigmoid (independent of eig chain)
    mma_gemm<EPI_SIG><<<dim3(DD/256, NT/128), 256, GEMM_SMEM>>>(
        xn_h, wh + W_GATE, sig, NT, DD, DD, gate_b, nullptr, nullptr);

    // 5) conv + SiLU + mem inject
    ten_conv_mem_kernel<<<dim3(TT/64, C2K/32, BB), 256>>>(
        beta0, pm, conv_w, conv_b, mem_gate, bRp, bIp);
    // 6) recurrence scan
    ten_scan_kernel<<<BB * KK, 256>>>(bRp, bIp, log_decay, frequency, cRp, cIp);
    // 7) coupling -> eig fp32 (output) + fp16 copy
    ten_coupling_kernel<<<dim3(TT/256, HH, BB), 256>>>(cRp, cIp, coupling, out_eig, eig_h);

    // 8) x1 = x + sig * (eig @ out_proj^T)
    mma_gemm<EPI_GATE><<<dim3(DD/256, NT/128), 256, GEMM_SMEM>>>(
        eig_h, wh + W_OUTPROJ, x1, NT, DD, C2K, sig, nullptr, x);

    // 9) LN2 -> fp16
    ten_ln_kernel<<<NT, 256>>>(x1, n2_g, n2_b, y_h);

    // 10) h1 = silu(y @ w1^T + b1) fp16  [16384,4096]
    mma_gemm<EPI_SILU_H><<<dim3(MM/256, NT/128), 256, GEMM_SMEM>>>(
        y_h, wh + W_MLP1, h1_h, NT, MM, DD, mlp_b1, nullptr, nullptr);
    // 11) x2 = x1 + h1 @ w2^T + b2  [16384,1024]
    mma_gemm<EPI_BIAS_RES><<<dim3(DD/256, NT/128), 256, GEMM_SMEM>>>(
        h1_h, wh + W_MLP2, out_x2, NT, DD, MM, mlp_b2, nullptr, x1);
}

// round 5
// speedup vs baseline: 5.6417x; 1.0496x over previous
#include <cuda_runtime.h>
#include <cuda_fp16.h>
#include <math.h>
#include <stdint.h>

// ---------------- problem constants ----------------
#define BB 4
#define TT 4096
#define DD 1024
#define KK 128
#define HH 8
#define KER 4
#define MM 4096          // mlp hidden
#define C2K 256          // 2*K
#define NT (BB*TT)       // 16384 rows

// ---------------- scratch (static device, no allocs) ----------------
__device__ __half g_xn_h[(size_t)NT*DD];     // LN1 out fp16
__device__ __half g_y_h[(size_t)NT*DD];      // LN2 out fp16
__device__ __half g_h1_h[(size_t)NT*MM];     // mlp mid fp16
__device__ __half g_eig_h[(size_t)NT*C2K];   // fp16 copy of eig
__device__ __half g_pe_h[(size_t)NT*C2K];    // fp16 prev_eig
__device__ float  g_beta0[(size_t)NT*C2K];
__device__ float  g_pm[(size_t)NT*C2K];
__device__ float  g_bR[(size_t)BB*KK*TT];
__device__ float  g_bI[(size_t)BB*KK*TT];
__device__ float  g_cR[(size_t)BB*KK*TT];
__device__ float  g_cI[(size_t)BB*KK*TT];
__device__ float  g_sig[(size_t)NT*DD];
__device__ float  g_x1[(size_t)NT*DD];
// fp16 weights, packed
#define W_INPROJ  0
#define W_MEMPROJ (W_INPROJ + C2K*DD)
#define W_OUTPROJ (W_MEMPROJ + C2K*C2K)
#define W_GATE    (W_OUTPROJ + DD*C2K)
#define W_MLP1    (W_GATE + DD*DD)
#define W_MLP2    (W_MLP1 + (size_t)MM*DD)
#define W_TOTAL   (W_MLP2 + (size_t)DD*MM)
__device__ __half g_wh[W_TOTAL];

__device__ __forceinline__ float sigmf(float x) { return 1.f / (1.f + __expf(-x)); }
__device__ __forceinline__ uint32_t smem_u32(const void* p) {
    uint32_t a;
    asm("{ .reg .u64 t; cvta.to.shared.u64 t, %1; cvt.u32.u64 %0, t; }" : "=r"(a) : "l"(p));
    return a;
}
__device__ __forceinline__ void cp16(uint32_t s, const void* g) {
    asm volatile("cp.async.cg.shared.global [%0], [%1], 16;" :: "r"(s), "l"(g));
}
__device__ __forceinline__ uint32_t h2u(__half2 h) { return *(uint32_t*)&h; }
__device__ __forceinline__ void ldsm_x4(uint32_t& r0, uint32_t& r1, uint32_t& r2, uint32_t& r3,
                                        uint32_t addr) {
    asm volatile("ldmatrix.sync.aligned.m8n8.x4.shared.b16 {%0,%1,%2,%3}, [%4];"
                 : "=r"(r0), "=r"(r1), "=r"(r2), "=r"(r3) : "r"(addr));
}

// ============================ batched fp32 -> fp16 ============================
struct CvtArgs {
    const float* src[7];
    __half* dst[7];
    int n8[7];
};
__global__ void cvt_all_kernel(CvtArgs a)
{
    const int seg = blockIdx.y;
    const int i = blockIdx.x * blockDim.x + threadIdx.x;
    if (i < a.n8[seg]) {
        const float4* s4 = (const float4*)a.src[seg] + 2 * (size_t)i;
        float4 p = s4[0], q = s4[1];
        uint4 o = {h2u(__floats2half2_rn(p.x, p.y)), h2u(__floats2half2_rn(p.z, p.w)),
                   h2u(__floats2half2_rn(q.x, q.y)), h2u(__floats2half2_rn(q.z, q.w))};
        ((uint4*)a.dst[seg])[i] = o;
    }
}

// ============================ LayerNorm -> fp16 out ============================
__global__ void ten_ln_kernel(const float* __restrict__ x,
                              const float* __restrict__ gw,
                              const float* __restrict__ bw,
                              __half* __restrict__ yh)
{
    const int row = blockIdx.x;
    const int tid = threadIdx.x;
    const float4* xr = (const float4*)(x + (size_t)row * DD);
    float4 v = xr[tid];
    float s = v.x + v.y + v.z + v.w;
    float q = v.x*v.x + v.y*v.y + v.z*v.z + v.w*v.w;
    #pragma unroll
    for (int o = 16; o > 0; o >>= 1) {
        s += __shfl_xor_sync(0xffffffffu, s, o);
        q += __shfl_xor_sync(0xffffffffu, q, o);
    }
    __shared__ float ss[8], sq[8];
    const int w = tid >> 5, l = tid & 31;
    if (l == 0) { ss[w] = s; sq[w] = q; }
    __syncthreads();
    float st = 0.f, qt = 0.f;
    #pragma unroll
    for (int i = 0; i < 8; i++) { st += ss[i]; qt += sq[i]; }
    const float mean = st * (1.f / DD);
    const float var  = qt * (1.f / DD) - mean * mean;
    const float rstd = rsqrtf(var + 1e-5f);
    float4 g4 = ((const float4*)gw)[tid];
    float4 b4 = ((const float4*)bw)[tid];
    float ox = (v.x - mean) * rstd * g4.x + b4.x;
    float oy = (v.y - mean) * rstd * g4.y + b4.y;
    float oz = (v.z - mean) * rstd * g4.z + b4.z;
    float ow = (v.w - mean) * rstd * g4.w + b4.w;
    uint2 ov = {h2u(__floats2half2_rn(ox, oy)), h2u(__floats2half2_rn(oz, ow))};
    ((uint2*)(yh + (size_t)row * DD))[tid] = ov;
}

// ============================ fp16 mma.sync GEMM ============================
// C[M,N] = A[M,K] @ B[N,K]^T ; block 128x256, BK=64 halves, 3-stage cp.async,
// 8 warps (2x4), warp tile 64x64 (4x8 m16n8k16), ldmatrix fragment loads.
enum { EPI_NONE = 0, EPI_SIG = 1, EPI_GATE = 2, EPI_SILU_H = 3, EPI_BIAS_RES = 4 };

#define ASTR 36                    // b32 per SMEM row (32 data + 4 pad)
#define ROWB (ASTR*4)              // 144 bytes per row
#define A_B32 (128*ASTR)
#define B_B32 (256*ASTR)
#define ST_B32 (A_B32 + B_B32)
#define GEMM_SMEM (3*ST_B32*4)     // 165888 B

template<int EPI>
__global__ void __launch_bounds__(256, 1)
mma_gemm(const __half* __restrict__ A, const __half* __restrict__ B, void* Cv,
         int M, int N, int K,
         const float* __restrict__ aux0, const float* __restrict__ aux1,
         const float* __restrict__ aux2)
{
    extern __shared__ uint32_t smu[];
    const uint32_t sm_base = smem_u32(smu);
    const int tid = threadIdx.x;
    const int lane = tid & 31, wid = tid >> 5;
    const int wm = wid >> 2, wn = wid & 3;          // 2 x 4 warp grid
    const int m0 = blockIdx.y * 128, n0 = blockIdx.x * 256;
    const int nchunk = K >> 6;
    const int g = lane >> 2, t = lane & 3;

    const __half* Ag = A + (size_t)m0 * K;
    const __half* Bg = B + (size_t)n0 * K;

    auto load_stage = [&](int s, int c) {
        const uint32_t sb = sm_base + (uint32_t)(s * ST_B32) * 4;
        const __half* ac = Ag + (size_t)c * 64;
        #pragma unroll
        for (int j = 0; j < 4; j++) {
            int idx = tid + j * 256; int r = idx >> 3; int u = idx & 7;
            cp16(sb + (uint32_t)(r * ASTR + u * 4) * 4, ac + (size_t)r * K + u * 8);
        }
        const __half* bc = Bg + (size_t)c * 64;
        #pragma unroll
        for (int j = 0; j < 8; j++) {
            int idx = tid + j * 256; int r = idx >> 3; int u = idx & 7;
            cp16(sb + (uint32_t)(A_B32 + r * ASTR + u * 4) * 4, bc + (size_t)r * K + u * 8);
        }
        asm volatile("cp.async.commit_group;");
    };

    float acc[4][8][4];
    #pragma unroll
    for (int mi = 0; mi < 4; mi++)
        #pragma unroll
        for (int ni = 0; ni < 8; ni++)
            #pragma unroll
            for (int q = 0; q < 4; q++) acc[mi][ni][q] = 0.f;

    load_stage(0, 0);
    if (1 < nchunk) load_stage(1, 1);

    // ldmatrix per-lane offsets (bytes)
    // A x4: lanes 0-15 -> rows 0-15 (k-lo), lanes 16-31 -> rows 0-15 (k-hi +16B)
    const uint32_t aOff = (uint32_t)(wm * 64 + (lane & 15)) * ROWB + (uint32_t)(lane >> 4) * 16;
    // B x4: q0 ni0/k-lo, q1 ni0/k-hi, q2 ni1/k-lo, q3 ni1/k-hi
    const uint32_t bOff = (uint32_t)A_B32 * 4 +
        (uint32_t)(wn * 64 + (lane & 7) + ((lane >> 4) & 1) * 8) * ROWB +
        (uint32_t)((lane >> 3) & 1) * 16;

    int stage = 0;
    for (int i = 0; i < nchunk; i++) {
        if (i == nchunk - 1) asm volatile("cp.async.wait_group 0;" ::: "memory");
        else                 asm volatile("cp.async.wait_group 1;" ::: "memory");
        __syncthreads();
        if (i + 2 < nchunk) {
            int ns = stage + 2; if (ns >= 3) ns -= 3;
            load_stage(ns, i + 2);
        }
        const uint32_t stBase = sm_base + (uint32_t)(stage * ST_B32) * 4;
        #pragma unroll
        for (int ks = 0; ks < 4; ks++) {
            const uint32_t kb = (uint32_t)ks * 32;
            uint32_t af[4][4], bf[8][2];
            #pragma unroll
            for (int mi = 0; mi < 4; mi++)
                ldsm_x4(af[mi][0], af[mi][1], af[mi][2], af[mi][3],
                        stBase + aOff + (uint32_t)mi * (16 * ROWB) + kb);
            #pragma unroll
            for (int np = 0; np < 4; np++)
                ldsm_x4(bf[2*np][0], bf[2*np][1], bf[2*np+1][0], bf[2*np+1][1],
                        stBase + bOff + (uint32_t)np * (16 * ROWB) + kb);
            #pragma unroll
            for (int mi = 0; mi < 4; mi++)
                #pragma unroll
                for (int ni = 0; ni < 8; ni++)
                    asm volatile(
                        "mma.sync.aligned.m16n8k16.row.col.f32.f16.f16.f32 "
                        "{%0,%1,%2,%3}, {%4,%5,%6,%7}, {%8,%9}, {%0,%1,%2,%3};"
                        : "+f"(acc[mi][ni][0]), "+f"(acc[mi][ni][1]),
                          "+f"(acc[mi][ni][2]), "+f"(acc[mi][ni][3])
                        : "r"(af[mi][0]), "r"(af[mi][1]), "r"(af[mi][2]), "r"(af[mi][3]),
                          "r"(bf[ni][0]), "r"(bf[ni][1]));
        }
        if (++stage == 3) stage = 0;
    }

    // -------- epilogue --------
    float* Cf = (float*)Cv;
    __half* Ch = (__half*)Cv;
    #pragma unroll
    for (int mi = 0; mi < 4; mi++) {
        const int rbase = m0 + wm * 64 + mi * 16 + g;
        #pragma unroll
        for (int ni = 0; ni < 8; ni++) {
            const int cc = n0 + wn * 64 + ni * 8 + t * 2;
            #pragma unroll
            for (int half_ = 0; half_ < 2; half_++) {
                const int r = rbase + half_ * 8;
                float v0 = acc[mi][ni][half_ * 2 + 0];
                float v1 = acc[mi][ni][half_ * 2 + 1];
                const size_t off = (size_t)r * N + cc;
                if (EPI == EPI_NONE) {
                    float2 o = {v0, v1};
                    *(float2*)(Cf + off) = o;
                } else if (EPI == EPI_SIG) {
                    float2 gb = *(const float2*)(aux0 + cc);
                    float2 o = {sigmf(v0 + gb.x), sigmf(v1 + gb.y)};
                    *(float2*)(Cf + off) = o;
                } else if (EPI == EPI_GATE) {
                    float2 sg = *(const float2*)(aux0 + off);
                    float2 xr = *(const float2*)(aux2 + off);
                    float2 o = {xr.x + sg.x * v0, xr.y + sg.y * v1};
                    *(float2*)(Cf + off) = o;
                } else if (EPI == EPI_SILU_H) {
                    float2 bb = *(const float2*)(aux0 + cc);
                    float t0 = v0 + bb.x, t1 = v1 + bb.y;
                    __half2 o = __floats2half2_rn(t0 * sigmf(t0), t1 * sigmf(t1));
                    *(uint32_t*)(Ch + off) = h2u(o);
                } else if (EPI == EPI_BIAS_RES) {
                    float2 bb = *(const float2*)(aux0 + cc);
                    float2 xr = *(const float2*)(aux2 + off);
                    float2 o = {xr.x + v0 + bb.x, xr.y + v1 + bb.y};
                    *(float2*)(Cf + off) = o;
                }
            }
        }
    }
}

// ---------------- depthwise causal conv + bias + SiLU + mem inject ----------
__global__ void __launch_bounds__(256)
ten_conv_mem_kernel(const float* __restrict__ beta0,
                    const float* __restrict__ pm,
                    const float* __restrict__ conv_w,
                    const float* __restrict__ conv_b,
                    const float* __restrict__ mem_gate,
                    float* __restrict__ bR, float* __restrict__ bI)
{
    const int b   = blockIdx.z;
    const int cg0 = blockIdx.y * 32;
    const int t0  = blockIdx.x * 64;
    __shared__ float sb[67][33];
    __shared__ float sp[64][33];
    const int tid = threadIdx.x;

    for (int i = tid; i < 67 * 32; i += 256) {
        const int r = i >> 5, c = i & 31;
        const int t = t0 + r - 3;
        sb[r][c] = (t >= 0) ? beta0[((size_t)(b * TT + t)) * C2K + cg0 + c] : 0.f;
    }
    for (int i = tid; i < 64 * 32; i += 256) {
        const int r = i >> 5, c = i & 31;
        sp[r][c] = pm[((size_t)(b * TT + t0 + r)) * C2K + cg0 + c];
    }
    __syncthreads();

    const float mg = 1.f / (1.f + expf(-mem_gate[0]));
    const int cl = tid >> 3;
    const int tg = (tid & 7) * 8;
    const int cglob = cg0 + cl;
    const float w0 = conv_w[cglob * 4 + 0];
    const float w1 = conv_w[cglob * 4 + 1];
    const float w2 = conv_w[cglob * 4 + 2];
    const float w3 = conv_w[cglob * 4 + 3];
    const float cb = conv_b[cglob];
    const int k = cglob & (KK - 1);
    float* dst = ((cglob < KK) ? bR : bI) + ((size_t)(b * KK + k)) * TT + t0 + tg;
    #pragma unroll
    for (int j = 0; j < 8; j++) {
        const int r = tg + j;
        float v = sb[r][cl] * w0 + sb[r + 1][cl] * w1 + sb[r + 2][cl] * w2 + sb[r + 3][cl] * w3 + cb;
        v = v * (1.f / (1.f + __expf(-v)));
        v += mg * sp[r][cl];
        dst[j] = v;
    }
}

// ---------------- complex first-order recurrence scan -----------------------
__global__ void __launch_bounds__(256)
ten_scan_kernel(const float* __restrict__ bR, const float* __restrict__ bI,
                const float* __restrict__ log_decay, const float* __restrict__ freq,
                float* __restrict__ cR, float* __restrict__ cI)
{
    const int bk = blockIdx.x;
    const int k = bk & (KK - 1);
    const float mag = 1.f / (1.f + expf(-log_decay[k]));
    float snf, csf;
    sincosf(freq[k], &snf, &csf);
    const float lr = mag * csf, li = mag * snf;
    const int tid = threadIdx.x;
    const size_t base = (size_t)bk * TT + tid * 16;

    float xr[16], xi[16];
    #pragma unroll
    for (int v = 0; v < 4; v++) {
        float4 a = *(const float4*)(bR + base + v * 4);
        xr[v*4+0] = a.x; xr[v*4+1] = a.y; xr[v*4+2] = a.z; xr[v*4+3] = a.w;
        float4 c = *(const float4*)(bI + base + v * 4);
        xi[v*4+0] = c.x; xi[v*4+1] = c.y; xi[v*4+2] = c.z; xi[v*4+3] = c.w;
    }

    float cr = 0.f, ci = 0.f;
    #pragma unroll
    for (int j = 0; j < 16; j++) {
        float nr = fmaf(lr, cr, fmaf(-li, ci, xr[j]));
        float ni = fmaf(lr, ci, fmaf( li, cr, xi[j]));
        cr = nr; ci = ni;
        xr[j] = cr; xi[j] = ci;
    }

    float fr = lr, fi = li;
    #pragma unroll
    for (int s = 0; s < 4; s++) {
        float nr = fr * fr - fi * fi;
        float ni = 2.f * fr * fi;
        fr = nr; fi = ni;
    }

    __shared__ float sgr[256], sgi[256], sor[256], soi[256];
    sgr[tid] = fr; sgi[tid] = fi; sor[tid] = cr; soi[tid] = ci;
    __syncthreads();
    for (int d = 1; d < 256; d <<= 1) {
        float ngr = 0.f, ngi = 0.f, nor_ = 0.f, noi_ = 0.f;
        if (tid >= d) {
            const float pgr = sgr[tid - d], pgi = sgi[tid - d];
            const float por = sor[tid - d], poi = soi[tid - d];
            const float gr = sgr[tid], gi = sgi[tid];
            const float orr = sor[tid], oii = soi[tid];
            ngr  = gr * pgr - gi * pgi;
            ngi  = gr * pgi + gi * pgr;
            nor_ = gr * por - gi * poi + orr;
            noi_ = gr * poi + gi * por + oii;
        }
        __syncthreads();
        if (tid >= d) { sgr[tid] = ngr; sgi[tid] = ngi; sor[tid] = nor_; soi[tid] = noi_; }
        __syncthreads();
    }
    const float pr = (tid > 0) ? sor[tid - 1] : 0.f;
    const float pi = (tid > 0) ? soi[tid - 1] : 0.f;

    float lpr = lr, lpi = li;
    #pragma unroll
    for (int j = 0; j < 16; j++) {
        xr[j] = fmaf(lpr, pr, fmaf(-lpi, pi, xr[j]));
        xi[j] = fmaf(lpr, pi, fmaf( lpi, pr, xi[j]));
        float nr = lpr * lr - lpi * li;
        float ni = lpr * li + lpi * lr;
        lpr = nr; lpi = ni;
    }
    #pragma unroll
    for (int v = 0; v < 4; v++) {
        float4 a = {xr[v*4+0], xr[v*4+1], xr[v*4+2], xr[v*4+3]};
        *(float4*)(cR + base + v * 4) = a;
        float4 c = {xi[v*4+0], xi[v*4+1], xi[v*4+2], xi[v*4+3]};
        *(float4*)(cI + base + v * 4) = c;
    }
}

// ---------------- coupling + transpose -> eig fp32 (output) + fp16 copy -----
__global__ void __launch_bounds__(256)
ten_coupling_kernel(const float* __restrict__ cR, const float* __restrict__ cI,
                    const float* __restrict__ coupling,
                    float* __restrict__ eig, __half* __restrict__ eig_h)
{
    const int b = blockIdx.z, h = blockIdx.y;
    const int t0 = blockIdx.x * 256;
    const int tid = threadIdx.x;
    __shared__ float sr[16][256];
    __shared__ float si[16][256];
    __shared__ float w[16][16];
    w[tid >> 4][tid & 15] = coupling[h * 256 + tid];
    #pragma unroll
    for (int kk = 0; kk < 16; kk++) {
        const size_t src = ((size_t)(b * KK + h * 16 + kk)) * TT + t0 + tid;
        sr[kk][tid] = cR[src];
        si[kk][tid] = cI[src];
    }
    __syncthreads();
    float orr[16], oii[16];
    #pragma unroll
    for (int j = 0; j < 16; j++) { orr[j] = 0.f; oii[j] = 0.f; }
    #pragma unroll
    for (int kk = 0; kk < 16; kk++) {
        const float vr = sr[kk][tid];
        const float vi = si[kk][tid];
        #pragma unroll
        for (int j = 0; j < 16; j++) {
            orr[j] = fmaf(w[j][kk], vr, orr[j]);
            oii[j] = fmaf(w[j][kk], vi, oii[j]);
        }
    }
    const size_t dst = ((size_t)(b * TT + t0 + tid)) * C2K + h * 16;
    #pragma unroll
    for (int j = 0; j < 16; j += 4) {
        float4 v = {orr[j], orr[j+1], orr[j+2], orr[j+3]};
        *(float4*)(eig + dst + j) = v;
        float4 u = {oii[j], oii[j+1], oii[j+2], oii[j+3]};
        *(float4*)(eig + dst + KK + j) = u;
        uint2 vv = {h2u(__floats2half2_rn(orr[j], orr[j+1])),
                    h2u(__floats2half2_rn(orr[j+2], orr[j+3]))};
        *(uint2*)(eig_h + dst + j) = vv;
        uint2 uu = {h2u(__floats2half2_rn(oii[j], oii[j+1])),
                    h2u(__floats2half2_rn(oii[j+2], oii[j+3]))};
        *(uint2*)(eig_h + dst + KK + j) = uu;
    }
}

// ---------------- launch -----------------------------------------------------
extern "C" void kernel_launch(void* const* d_in, const int* in_sizes, int n_in,
                              void* d_out, int out_size)
{
    const float* x          = (const float*)d_in[0];
    const float* prev_eig   = (const float*)d_in[1];
    const float* in_proj_w  = (const float*)d_in[2];
    const float* conv_w     = (const float*)d_in[3];
    const float* conv_b     = (const float*)d_in[4];
    const float* mem_gate   = (const float*)d_in[5];
    const float* mem_proj_w = (const float*)d_in[6];
    const float* log_decay  = (const float*)d_in[7];
    const float* frequency  = (const float*)d_in[8];
    const float* coupling   = (const float*)d_in[9];
    const float* out_proj_w = (const float*)d_in[10];
    const float* gate_w     = (const float*)d_in[11];
    const float* gate_b     = (const float*)d_in[12];
    const float* mlp_w1     = (const float*)d_in[13];
    const float* mlp_b1     = (const float*)d_in[14];
    const float* mlp_w2     = (const float*)d_in[15];
    const float* mlp_b2     = (const float*)d_in[16];
    const float* n1_g       = (const float*)d_in[17];
    const float* n1_b       = (const float*)d_in[18];
    const float* n2_g       = (const float*)d_in[19];
    const float* n2_b       = (const float*)d_in[20];

    float* out_x2  = (float*)d_out;
    float* out_eig = out_x2 + (size_t)NT * DD;

    __half *xn_h, *y_h, *h1_h, *eig_h, *pe_h, *wh;
    float *beta0, *pm, *bRp, *bIp, *cRp, *cIp, *sig, *x1;
    cudaGetSymbolAddress((void**)&xn_h,  g_xn_h);
    cudaGetSymbolAddress((void**)&y_h,   g_y_h);
    cudaGetSymbolAddress((void**)&h1_h,  g_h1_h);
    cudaGetSymbolAddress((void**)&eig_h, g_eig_h);
    cudaGetSymbolAddress((void**)&pe_h,  g_pe_h);
    cudaGetSymbolAddress((void**)&wh,    g_wh);
    cudaGetSymbolAddress((void**)&beta0, g_beta0);
    cudaGetSymbolAddress((void**)&pm,    g_pm);
    cudaGetSymbolAddress((void**)&bRp,   g_bR);
    cudaGetSymbolAddress((void**)&bIp,   g_bI);
    cudaGetSymbolAddress((void**)&cRp,   g_cR);
    cudaGetSymbolAddress((void**)&cIp,   g_cI);
    cudaGetSymbolAddress((void**)&sig,   g_sig);
    cudaGetSymbolAddress((void**)&x1,    g_x1);

    cudaFuncSetAttribute(mma_gemm<EPI_NONE>,     cudaFuncAttributeMaxDynamicSharedMemorySize, GEMM_SMEM);
    cudaFuncSetAttribute(mma_gemm<EPI_SIG>,      cudaFuncAttributeMaxDynamicSharedMemorySize, GEMM_SMEM);
    cudaFuncSetAttribute(mma_gemm<EPI_GATE>,     cudaFuncAttributeMaxDynamicSharedMemorySize, GEMM_SMEM);
    cudaFuncSetAttribute(mma_gemm<EPI_SILU_H>,   cudaFuncAttributeMaxDynamicSharedMemorySize, GEMM_SMEM);
    cudaFuncSetAttribute(mma_gemm<EPI_BIAS_RES>, cudaFuncAttributeMaxDynamicSharedMemorySize, GEMM_SMEM);

    // batched weight/activation conversion (7 segments, one launch)
    CvtArgs ca;
    ca.src[0] = in_proj_w;  ca.dst[0] = wh + W_INPROJ;  ca.n8[0] = (int)((size_t)C2K * DD / 8);
    ca.src[1] = mem_proj_w; ca.dst[1] = wh + W_MEMPROJ; ca.n8[1] = (int)((size_t)C2K * C2K / 8);
    ca.src[2] = out_proj_w; ca.dst[2] = wh + W_OUTPROJ; ca.n8[2] = (int)((size_t)DD * C2K / 8);
    ca.src[3] = gate_w;     ca.dst[3] = wh + W_GATE;    ca.n8[3] = (int)((size_t)DD * DD / 8);
    ca.src[4] = mlp_w1;     ca.dst[4] = wh + W_MLP1;    ca.n8[4] = (int)((size_t)MM * DD / 8);
    ca.src[5] = mlp_w2;     ca.dst[5] = wh + W_MLP2;    ca.n8[5] = (int)((size_t)DD * MM / 8);
    ca.src[6] = prev_eig;   ca.dst[6] = pe_h;           ca.n8[6] = (int)((size_t)NT * C2K / 8);
    cvt_all_kernel<<<dim3(2048, 7), 256>>>(ca);

    // 1) LN1 -> fp16
    ten_ln_kernel<<<NT, 256>>>(x, n1_g, n1_b, xn_h);

    // 2) beta0 = xn @ in_proj_w^T   [16384,256] fp32 out
    mma_gemm<EPI_NONE><<<dim3(C2K/256, NT/128), 256, GEMM_SMEM>>>(
        xn_h, wh + W_INPROJ, beta0, NT, C2K, DD, nullptr, nullptr, nullptr);
    // 3) pm = prev_eig @ mem_proj_w^T  [16384,256]
    mma_gemm<EPI_NONE><<<dim3(C2K/256, NT/128), 256, GEMM_SMEM>>>(
        pe_h, wh + W_MEMPROJ, pm, NT, C2K, C2K, nullptr, nullptr, nullptr);
    // 4) gate sigmoid (independent of eig chain)
    mma_gemm<EPI_SIG><<<dim3(DD/256, NT/128), 256, GEMM_SMEM>>>(
        xn_h, wh + W_GATE, sig, NT, DD, DD, gate_b, nullptr, nullptr);

    // 5) conv + SiLU + mem inject
    ten_conv_mem_kernel<<<dim3(TT/64, C2K/32, BB), 256>>>(
        beta0, pm, conv_w, conv_b, mem_gate, bRp, bIp);
    // 6) recurrence scan
    ten_scan_kernel<<<BB * KK, 256>>>(bRp, bIp, log_decay, frequency, cRp, cIp);
    // 7) coupling -> eig fp32 (output) + fp16 copy
    ten_coupling_kernel<<<dim3(TT/256, HH, BB), 256>>>(cRp, cIp, coupling, out_eig, eig_h);

    // 8) x1 = x + sig * (eig @ out_proj^T)
    mma_gemm<EPI_GATE><<<dim3(DD/256, NT/128), 256, GEMM_SMEM>>>(
        eig_h, wh + W_OUTPROJ, x1, NT, DD, C2K, sig, nullptr, x);

    // 9) LN2 -> fp16
    ten_ln_kernel<<<NT, 256>>>(x1, n2_g, n2_b, y_h);

    // 10) h1 = silu(y @ w1^T + b1) fp16  [16384,4096]
    mma_gemm<EPI_SILU_H><<<dim3(MM/256, NT/128), 256, GEMM_SMEM>>>(
        y_h, wh + W_MLP1, h1_h, NT, MM, DD, mlp_b1, nullptr, nullptr);
    // 11) x2 = x1 + h1 @ w2^T + b2  [16384,1024]
    mma_gemm<EPI_BIAS_RES><<<dim3(DD/256, NT/128), 256, GEMM_SMEM>>>(
        h1_h, wh + W_MLP2, out_x2, NT, DD, MM, mlp_b2, nullptr, x1);
}

// round 6
// speedup vs baseline: 6.6934x; 1.1864x over previous
#include <cuda_runtime.h>
#include <cuda_fp16.h>
#include <math.h>
#include <stdint.h>

// ---------------- problem constants ----------------
#define BB 4
#define TT 4096
#define DD 1024
#define KK 128
#define HH 8
#define KER 4
#define MM 4096          // mlp hidden
#define C2K 256          // 2*K
#define NT (BB*TT)       // 16384 rows

// ---------------- scratch (static device, no allocs) ----------------
__device__ __half g_xn_h[(size_t)NT*DD];     // LN1 out fp16
__device__ __half g_y_h[(size_t)NT*DD];      // LN2 out fp16
__device__ __half g_h1_h[(size_t)NT*MM];     // mlp mid fp16
__device__ __half g_eig_h[(size_t)NT*C2K];   // fp16 copy of eig
__device__ __half g_pe_h[(size_t)NT*C2K];    // fp16 prev_eig
__device__ __half g_sig_h[(size_t)NT*DD];    // sigmoid gate fp16
__device__ float  g_beta0[(size_t)NT*C2K];
__device__ float  g_pm[(size_t)NT*C2K];
__device__ float  g_bR[(size_t)BB*KK*TT];
__device__ float  g_bI[(size_t)BB*KK*TT];
__device__ float  g_cR[(size_t)BB*KK*TT];
__device__ float  g_cI[(size_t)BB*KK*TT];
__device__ float  g_x1[(size_t)NT*DD];
// fp16 weights, packed
#define W_INPROJ  0
#define W_MEMPROJ (W_INPROJ + C2K*DD)
#define W_OUTPROJ (W_MEMPROJ + C2K*C2K)
#define W_GATE    (W_OUTPROJ + DD*C2K)
#define W_MLP1    (W_GATE + DD*DD)
#define W_MLP2    (W_MLP1 + (size_t)MM*DD)
#define W_TOTAL   (W_MLP2 + (size_t)DD*MM)
__device__ __half g_wh[W_TOTAL];

__device__ __forceinline__ float sigmf(float x) { return 1.f / (1.f + __expf(-x)); }
__device__ __forceinline__ uint32_t smem_u32(const void* p) {
    uint32_t a;
    asm("{ .reg .u64 t; cvta.to.shared.u64 t, %1; cvt.u32.u64 %0, t; }" : "=r"(a) : "l"(p));
    return a;
}
__device__ __forceinline__ void cp16(uint32_t s, const void* g) {
    asm volatile("cp.async.cg.shared.global [%0], [%1], 16;" :: "r"(s), "l"(g));
}
__device__ __forceinline__ uint32_t h2u(__half2 h) { return *(uint32_t*)&h; }
__device__ __forceinline__ void ldsm_x4(uint32_t& r0, uint32_t& r1, uint32_t& r2, uint32_t& r3,
                                        uint32_t addr) {
    asm volatile("ldmatrix.sync.aligned.m8n8.x4.shared.b16 {%0,%1,%2,%3}, [%4];"
                 : "=r"(r0), "=r"(r1), "=r"(r2), "=r"(r3) : "r"(addr));
}

// ============================ batched fp32 -> fp16 ============================
struct CvtArgs {
    const float* src[7];
    __half* dst[7];
    int n8[7];
};
__global__ void cvt_all_kernel(CvtArgs a)
{
    const int seg = blockIdx.y;
    const int i = blockIdx.x * blockDim.x + threadIdx.x;
    if (i < a.n8[seg]) {
        const float4* s4 = (const float4*)a.src[seg] + 2 * (size_t)i;
        float4 p = s4[0], q = s4[1];
        uint4 o = {h2u(__floats2half2_rn(p.x, p.y)), h2u(__floats2half2_rn(p.z, p.w)),
                   h2u(__floats2half2_rn(q.x, q.y)), h2u(__floats2half2_rn(q.z, q.w))};
        ((uint4*)a.dst[seg])[i] = o;
    }
}

// ============================ LayerNorm -> fp16 out ============================
__global__ void ten_ln_kernel(const float* __restrict__ x,
                              const float* __restrict__ gw,
                              const float* __restrict__ bw,
                              __half* __restrict__ yh)
{
    const int row = blockIdx.x;
    const int tid = threadIdx.x;
    const float4* xr = (const float4*)(x + (size_t)row * DD);
    float4 v = xr[tid];
    float s = v.x + v.y + v.z + v.w;
    float q = v.x*v.x + v.y*v.y + v.z*v.z + v.w*v.w;
    #pragma unroll
    for (int o = 16; o > 0; o >>= 1) {
        s += __shfl_xor_sync(0xffffffffu, s, o);
        q += __shfl_xor_sync(0xffffffffu, q, o);
    }
    __shared__ float ss[8], sq[8];
    const int w = tid >> 5, l = tid & 31;
    if (l == 0) { ss[w] = s; sq[w] = q; }
    __syncthreads();
    float st = 0.f, qt = 0.f;
    #pragma unroll
    for (int i = 0; i < 8; i++) { st += ss[i]; qt += sq[i]; }
    const float mean = st * (1.f / DD);
    const float var  = qt * (1.f / DD) - mean * mean;
    const float rstd = rsqrtf(var + 1e-5f);
    float4 g4 = ((const float4*)gw)[tid];
    float4 b4 = ((const float4*)bw)[tid];
    float ox = (v.x - mean) * rstd * g4.x + b4.x;
    float oy = (v.y - mean) * rstd * g4.y + b4.y;
    float oz = (v.z - mean) * rstd * g4.z + b4.z;
    float ow = (v.w - mean) * rstd * g4.w + b4.w;
    uint2 ov = {h2u(__floats2half2_rn(ox, oy)), h2u(__floats2half2_rn(oz, ow))};
    ((uint2*)(yh + (size_t)row * DD))[tid] = ov;
}

// ============================ fp16 mma.sync GEMM ============================
// C[M,N] = A[M,K] @ B[N,K]^T ; block 128x128, BK=64 halves, 3-stage cp.async,
// 8 warps (2x4), warp tile 64x32 (4x4 m16n8k16), ldmatrix loads, 2 CTAs/SM.
enum { EPI_NONE = 0, EPI_SIG = 1, EPI_GATE = 2, EPI_SILU_H = 3, EPI_BIAS_RES = 4 };

#define ASTR 36                    // b32 per SMEM row (32 data + 4 pad)
#define ROWB (ASTR*4)              // 144 bytes per row
#define A_B32 (128*ASTR)
#define B_B32 (128*ASTR)
#define ST_B32 (A_B32 + B_B32)     // 9216 b32
#define GEMM_SMEM (3*ST_B32*4)     // 110592 B

template<int EPI>
__global__ void __launch_bounds__(256, 2)
mma_gemm(const __half* __restrict__ A, const __half* __restrict__ B, void* Cv,
         int M, int N, int K,
         const float* __restrict__ aux0, const void* __restrict__ aux1,
         const float* __restrict__ aux2)
{
    extern __shared__ uint32_t smu[];
    const uint32_t sm_base = smem_u32(smu);
    const int tid = threadIdx.x;
    const int lane = tid & 31, wid = tid >> 5;
    const int wm = wid >> 2, wn = wid & 3;          // 2 x 4 warp grid
    const int m0 = blockIdx.y * 128, n0 = blockIdx.x * 128;
    const int nchunk = K >> 6;
    const int g = lane >> 2, t = lane & 3;

    const __half* Ag = A + (size_t)m0 * K;
    const __half* Bg = B + (size_t)n0 * K;

    auto load_stage = [&](int s, int c) {
        const uint32_t sb = sm_base + (uint32_t)(s * ST_B32) * 4;
        const __half* ac = Ag + (size_t)c * 64;
        #pragma unroll
        for (int j = 0; j < 4; j++) {
            int idx = tid + j * 256; int r = idx >> 3; int u = idx & 7;
            cp16(sb + (uint32_t)(r * ASTR + u * 4) * 4, ac + (size_t)r * K + u * 8);
        }
        const __half* bc = Bg + (size_t)c * 64;
        #pragma unroll
        for (int j = 0; j < 4; j++) {
            int idx = tid + j * 256; int r = idx >> 3; int u = idx & 7;
            cp16(sb + (uint32_t)(A_B32 + r * ASTR + u * 4) * 4, bc + (size_t)r * K + u * 8);
        }
        asm volatile("cp.async.commit_group;");
    };

    float acc[4][4][4];
    #pragma unroll
    for (int mi = 0; mi < 4; mi++)
        #pragma unroll
        for (int ni = 0; ni < 4; ni++)
            #pragma unroll
            for (int q = 0; q < 4; q++) acc[mi][ni][q] = 0.f;

    load_stage(0, 0);
    if (1 < nchunk) load_stage(1, 1);

    // ldmatrix per-lane offsets (bytes)
    // A x4: lanes 0-15 -> rows 0-15 (k-lo), lanes 16-31 -> same rows (k-hi +16B)
    const uint32_t aOff = (uint32_t)(wm * 64 + (lane & 15)) * ROWB + (uint32_t)(lane >> 4) * 16;
    // B x4: quads = (n8 tile, k-half): rows lane&7 + ((lane>>4)&1)*8, col ((lane>>3)&1)*16
    const uint32_t bOff = (uint32_t)A_B32 * 4 +
        (uint32_t)(wn * 32 + (lane & 7) + ((lane >> 4) & 1) * 8) * ROWB +
        (uint32_t)((lane >> 3) & 1) * 16;

    int stage = 0;
    for (int i = 0; i < nchunk; i++) {
        if (i == nchunk - 1) asm volatile("cp.async.wait_group 0;" ::: "memory");
        else                 asm volatile("cp.async.wait_group 1;" ::: "memory");
        __syncthreads();
        if (i + 2 < nchunk) {
            int ns = stage + 2; if (ns >= 3) ns -= 3;
            load_stage(ns, i + 2);
        }
        const uint32_t stBase = sm_base + (uint32_t)(stage * ST_B32) * 4;
        #pragma unroll
        for (int ks = 0; ks < 4; ks++) {
            const uint32_t kb = (uint32_t)ks * 32;
            uint32_t af[4][4], bf[4][2];
            #pragma unroll
            for (int mi = 0; mi < 4; mi++)
                ldsm_x4(af[mi][0], af[mi][1], af[mi][2], af[mi][3],
                        stBase + aOff + (uint32_t)mi * (16 * ROWB) + kb);
            #pragma unroll
            for (int np = 0; np < 2; np++)
                ldsm_x4(bf[2*np][0], bf[2*np][1], bf[2*np+1][0], bf[2*np+1][1],
                        stBase + bOff + (uint32_t)np * (16 * ROWB) + kb);
            #pragma unroll
            for (int mi = 0; mi < 4; mi++)
                #pragma unroll
                for (int ni = 0; ni < 4; ni++)
                    asm volatile(
                        "mma.sync.aligned.m16n8k16.row.col.f32.f16.f16.f32 "
                        "{%0,%1,%2,%3}, {%4,%5,%6,%7}, {%8,%9}, {%0,%1,%2,%3};"
                        : "+f"(acc[mi][ni][0]), "+f"(acc[mi][ni][1]),
                          "+f"(acc[mi][ni][2]), "+f"(acc[mi][ni][3])
                        : "r"(af[mi][0]), "r"(af[mi][1]), "r"(af[mi][2]), "r"(af[mi][3]),
                          "r"(bf[ni][0]), "r"(bf[ni][1]));
        }
        if (++stage == 3) stage = 0;
    }

    // -------- epilogue --------
    float* Cf = (float*)Cv;
    __half* Ch = (__half*)Cv;
    const __half* sgh = (const __half*)aux1;   // EPI_GATE: fp16 sigmoid gate
    #pragma unroll
    for (int mi = 0; mi < 4; mi++) {
        const int rbase = m0 + wm * 64 + mi * 16 + g;
        #pragma unroll
        for (int ni = 0; ni < 4; ni++) {
            const int cc = n0 + wn * 32 + ni * 8 + t * 2;
            #pragma unroll
            for (int half_ = 0; half_ < 2; half_++) {
                const int r = rbase + half_ * 8;
                float v0 = acc[mi][ni][half_ * 2 + 0];
                float v1 = acc[mi][ni][half_ * 2 + 1];
                const size_t off = (size_t)r * N + cc;
                if (EPI == EPI_NONE) {
                    float2 o = {v0, v1};
                    *(float2*)(Cf + off) = o;
                } else if (EPI == EPI_SIG) {
                    float2 gb = *(const float2*)(aux0 + cc);
                    __half2 o = __floats2half2_rn(sigmf(v0 + gb.x), sigmf(v1 + gb.y));
                    *(uint32_t*)(Ch + off) = h2u(o);
                } else if (EPI == EPI_GATE) {
                    uint32_t su = *(const uint32_t*)(sgh + off);
                    float2 sg = __half22float2(*(__half2*)&su);
                    float2 xr = *(const float2*)(aux2 + off);
                    float2 o = {xr.x + sg.x * v0, xr.y + sg.y * v1};
                    *(float2*)(Cf + off) = o;
                } else if (EPI == EPI_SILU_H) {
                    float2 bb = *(const float2*)(aux0 + cc);
                    float t0 = v0 + bb.x, t1 = v1 + bb.y;
                    __half2 o = __floats2half2_rn(t0 * sigmf(t0), t1 * sigmf(t1));
                    *(uint32_t*)(Ch + off) = h2u(o);
                } else if (EPI == EPI_BIAS_RES) {
                    float2 bb = *(const float2*)(aux0 + cc);
                    float2 xr = *(const float2*)(aux2 + off);
                    float2 o = {xr.x + v0 + bb.x, xr.y + v1 + bb.y};
                    *(float2*)(Cf + off) = o;
                }
            }
        }
    }
}

// ---------------- depthwise causal conv + bias + SiLU + mem inject ----------
__global__ void __launch_bounds__(256)
ten_conv_mem_kernel(const float* __restrict__ beta0,
                    const float* __restrict__ pm,
                    const float* __restrict__ conv_w,
                    const float* __restrict__ conv_b,
                    const float* __restrict__ mem_gate,
                    float* __restrict__ bR, float* __restrict__ bI)
{
    const int b   = blockIdx.z;
    const int cg0 = blockIdx.y * 32;
    const int t0  = blockIdx.x * 64;
    __shared__ float sb[67][33];
    __shared__ float sp[64][33];
    const int tid = threadIdx.x;

    for (int i = tid; i < 67 * 32; i += 256) {
        const int r = i >> 5, c = i & 31;
        const int t = t0 + r - 3;
        sb[r][c] = (t >= 0) ? beta0[((size_t)(b * TT + t)) * C2K + cg0 + c] : 0.f;
    }
    for (int i = tid; i < 64 * 32; i += 256) {
        const int r = i >> 5, c = i & 31;
        sp[r][c] = pm[((size_t)(b * TT + t0 + r)) * C2K + cg0 + c];
    }
    __syncthreads();

    const float mg = 1.f / (1.f + expf(-mem_gate[0]));
    const int cl = tid >> 3;
    const int tg = (tid & 7) * 8;
    const int cglob = cg0 + cl;
    const float w0 = conv_w[cglob * 4 + 0];
    const float w1 = conv_w[cglob * 4 + 1];
    const float w2 = conv_w[cglob * 4 + 2];
    const float w3 = conv_w[cglob * 4 + 3];
    const float cb = conv_b[cglob];
    const int k = cglob & (KK - 1);
    float* dst = ((cglob < KK) ? bR : bI) + ((size_t)(b * KK + k)) * TT + t0 + tg;
    #pragma unroll
    for (int j = 0; j < 8; j++) {
        const int r = tg + j;
        float v = sb[r][cl] * w0 + sb[r + 1][cl] * w1 + sb[r + 2][cl] * w2 + sb[r + 3][cl] * w3 + cb;
        v = v * (1.f / (1.f + __expf(-v)));
        v += mg * sp[r][cl];
        dst[j] = v;
    }
}

// ---------------- complex first-order recurrence scan -----------------------
__global__ void __launch_bounds__(256)
ten_scan_kernel(const float* __restrict__ bR, const float* __restrict__ bI,
                const float* __restrict__ log_decay, const float* __restrict__ freq,
                float* __restrict__ cR, float* __restrict__ cI)
{
    const int bk = blockIdx.x;
    const int k = bk & (KK - 1);
    const float mag = 1.f / (1.f + expf(-log_decay[k]));
    float snf, csf;
    sincosf(freq[k], &snf, &csf);
    const float lr = mag * csf, li = mag * snf;
    const int tid = threadIdx.x;
    const size_t base = (size_t)bk * TT + tid * 16;

    float xr[16], xi[16];
    #pragma unroll
    for (int v = 0; v < 4; v++) {
        float4 a = *(const float4*)(bR + base + v * 4);
        xr[v*4+0] = a.x; xr[v*4+1] = a.y; xr[v*4+2] = a.z; xr[v*4+3] = a.w;
        float4 c = *(const float4*)(bI + base + v * 4);
        xi[v*4+0] = c.x; xi[v*4+1] = c.y; xi[v*4+2] = c.z; xi[v*4+3] = c.w;
    }

    float cr = 0.f, ci = 0.f;
    #pragma unroll
    for (int j = 0; j < 16; j++) {
        float nr = fmaf(lr, cr, fmaf(-li, ci, xr[j]));
        float ni = fmaf(lr, ci, fmaf( li, cr, xi[j]));
        cr = nr; ci = ni;
        xr[j] = cr; xi[j] = ci;
    }

    float fr = lr, fi = li;
    #pragma unroll
    for (int s = 0; s < 4; s++) {
        float nr = fr * fr - fi * fi;
        float ni = 2.f * fr * fi;
        fr = nr; fi = ni;
    }

    __shared__ float sgr[256], sgi[256], sor[256], soi[256];
    sgr[tid] = fr; sgi[tid] = fi; sor[tid] = cr; soi[tid] = ci;
    __syncthreads();
    for (int d = 1; d < 256; d <<= 1) {
        float ngr = 0.f, ngi = 0.f, nor_ = 0.f, noi_ = 0.f;
        if (tid >= d) {
            const float pgr = sgr[tid - d], pgi = sgi[tid - d];
            const float por = sor[tid - d], poi = soi[tid - d];
            const float gr = sgr[tid], gi = sgi[tid];
            const float orr = sor[tid], oii = soi[tid];
            ngr  = gr * pgr - gi * pgi;
            ngi  = gr * pgi + gi * pgr;
            nor_ = gr * por - gi * poi + orr;
            noi_ = gr * poi + gi * por + oii;
        }
        __syncthreads();
        if (tid >= d) { sgr[tid] = ngr; sgi[tid] = ngi; sor[tid] = nor_; soi[tid] = noi_; }
        __syncthreads();
    }
    const float pr = (tid > 0) ? sor[tid - 1] : 0.f;
    const float pi = (tid > 0) ? soi[tid - 1] : 0.f;

    float lpr = lr, lpi = li;
    #pragma unroll
    for (int j = 0; j < 16; j++) {
        xr[j] = fmaf(lpr, pr, fmaf(-lpi, pi, xr[j]));
        xi[j] = fmaf(lpr, pi, fmaf( lpi, pr, xi[j]));
        float nr = lpr * lr - lpi * li;
        float ni = lpr * li + lpi * lr;
        lpr = nr; lpi = ni;
    }
    #pragma unroll
    for (int v = 0; v < 4; v++) {
        float4 a = {xr[v*4+0], xr[v*4+1], xr[v*4+2], xr[v*4+3]};
        *(float4*)(cR + base + v * 4) = a;
        float4 c = {xi[v*4+0], xi[v*4+1], xi[v*4+2], xi[v*4+3]};
        *(float4*)(cI + base + v * 4) = c;
    }
}

// ---------------- coupling + transpose -> eig fp32 (output) + fp16 copy -----
__global__ void __launch_bounds__(256)
ten_coupling_kernel(const float* __restrict__ cR, const float* __restrict__ cI,
                    const float* __restrict__ coupling,
                    float* __restrict__ eig, __half* __restrict__ eig_h)
{
    const int b = blockIdx.z, h = blockIdx.y;
    const int t0 = blockIdx.x * 256;
    const int tid = threadIdx.x;
    __shared__ float sr[16][256];
    __shared__ float si[16][256];
    __shared__ float w[16][16];
    w[tid >> 4][tid & 15] = coupling[h * 256 + tid];
    #pragma unroll
    for (int kk = 0; kk < 16; kk++) {
        const size_t src = ((size_t)(b * KK + h * 16 + kk)) * TT + t0 + tid;
        sr[kk][tid] = cR[src];
        si[kk][tid] = cI[src];
    }
    __syncthreads();
    float orr[16], oii[16];
    #pragma unroll
    for (int j = 0; j < 16; j++) { orr[j] = 0.f; oii[j] = 0.f; }
    #pragma unroll
    for (int kk = 0; kk < 16; kk++) {
        const float vr = sr[kk][tid];
        const float vi = si[kk][tid];
        #pragma unroll
        for (int j = 0; j < 16; j++) {
            orr[j] = fmaf(w[j][kk], vr, orr[j]);
            oii[j] = fmaf(w[j][kk], vi, oii[j]);
        }
    }
    const size_t dst = ((size_t)(b * TT + t0 + tid)) * C2K + h * 16;
    #pragma unroll
    for (int j = 0; j < 16; j += 4) {
        float4 v = {orr[j], orr[j+1], orr[j+2], orr[j+3]};
        *(float4*)(eig + dst + j) = v;
        float4 u = {oii[j], oii[j+1], oii[j+2], oii[j+3]};
        *(float4*)(eig + dst + KK + j) = u;
        uint2 vv = {h2u(__floats2half2_rn(orr[j], orr[j+1])),
                    h2u(__floats2half2_rn(orr[j+2], orr[j+3]))};
        *(uint2*)(eig_h + dst + j) = vv;
        uint2 uu = {h2u(__floats2half2_rn(oii[j], oii[j+1])),
                    h2u(__floats2half2_rn(oii[j+2], oii[j+3]))};
        *(uint2*)(eig_h + dst + KK + j) = uu;
    }
}

// ---------------- launch -----------------------------------------------------
extern "C" void kernel_launch(void* const* d_in, const int* in_sizes, int n_in,
                              void* d_out, int out_size)
{
    const float* x          = (const float*)d_in[0];
    const float* prev_eig   = (const float*)d_in[1];
    const float* in_proj_w  = (const float*)d_in[2];
    const float* conv_w     = (const float*)d_in[3];
    const float* conv_b     = (const float*)d_in[4];
    const float* mem_gate   = (const float*)d_in[5];
    const float* mem_proj_w = (const float*)d_in[6];
    const float* log_decay  = (const float*)d_in[7];
    const float* frequency  = (const float*)d_in[8];
    const float* coupling   = (const float*)d_in[9];
    const float* out_proj_w = (const float*)d_in[10];
    const float* gate_w     = (const float*)d_in[11];
    const float* gate_b     = (const float*)d_in[12];
    const float* mlp_w1     = (const float*)d_in[13];
    const float* mlp_b1     = (const float*)d_in[14];
    const float* mlp_w2     = (const float*)d_in[15];
    const float* mlp_b2     = (const float*)d_in[16];
    const float* n1_g       = (const float*)d_in[17];
    const float* n1_b       = (const float*)d_in[18];
    const float* n2_g       = (const float*)d_in[19];
    const float* n2_b       = (const float*)d_in[20];

    float* out_x2  = (float*)d_out;
    float* out_eig = out_x2 + (size_t)NT * DD;

    __half *xn_h, *y_h, *h1_h, *eig_h, *pe_h, *sig_h, *wh;
    float *beta0, *pm, *bRp, *bIp, *cRp, *cIp, *x1;
    cudaGetSymbolAddress((void**)&xn_h,  g_xn_h);
    cudaGetSymbolAddress((void**)&y_h,   g_y_h);
    cudaGetSymbolAddress((void**)&h1_h,  g_h1_h);
    cudaGetSymbolAddress((void**)&eig_h, g_eig_h);
    cudaGetSymbolAddress((void**)&pe_h,  g_pe_h);
    cudaGetSymbolAddress((void**)&sig_h, g_sig_h);
    cudaGetSymbolAddress((void**)&wh,    g_wh);
    cudaGetSymbolAddress((void**)&beta0, g_beta0);
    cudaGetSymbolAddress((void**)&pm,    g_pm);
    cudaGetSymbolAddress((void**)&bRp,   g_bR);
    cudaGetSymbolAddress((void**)&bIp,   g_bI);
    cudaGetSymbolAddress((void**)&cRp,   g_cR);
    cudaGetSymbolAddress((void**)&cIp,   g_cI);
    cudaGetSymbolAddress((void**)&x1,    g_x1);

    cudaFuncSetAttribute(mma_gemm<EPI_NONE>,     cudaFuncAttributeMaxDynamicSharedMemorySize, GEMM_SMEM);
    cudaFuncSetAttribute(mma_gemm<EPI_SIG>,      cudaFuncAttributeMaxDynamicSharedMemorySize, GEMM_SMEM);
    cudaFuncSetAttribute(mma_gemm<EPI_GATE>,     cudaFuncAttributeMaxDynamicSharedMemorySize, GEMM_SMEM);
    cudaFuncSetAttribute(mma_gemm<EPI_SILU_H>,   cudaFuncAttributeMaxDynamicSharedMemorySize, GEMM_SMEM);
    cudaFuncSetAttribute(mma_gemm<EPI_BIAS_RES>, cudaFuncAttributeMaxDynamicSharedMemorySize, GEMM_SMEM);

    // batched weight/activation conversion (7 segments, one launch)
    CvtArgs ca;
    ca.src[0] = in_proj_w;  ca.dst[0] = wh + W_INPROJ;  ca.n8[0] = (int)((size_t)C2K * DD / 8);
    ca.src[1] = mem_proj_w; ca.dst[1] = wh + W_MEMPROJ; ca.n8[1] = (int)((size_t)C2K * C2K / 8);
    ca.src[2] = out_proj_w; ca.dst[2] = wh + W_OUTPROJ; ca.n8[2] = (int)((size_t)DD * C2K / 8);
    ca.src[3] = gate_w;     ca.dst[3] = wh + W_GATE;    ca.n8[3] = (int)((size_t)DD * DD / 8);
    ca.src[4] = mlp_w1;     ca.dst[4] = wh + W_MLP1;    ca.n8[4] = (int)((size_t)MM * DD / 8);
    ca.src[5] = mlp_w2;     ca.dst[5] = wh + W_MLP2;    ca.n8[5] = (int)((size_t)DD * MM / 8);
    ca.src[6] = prev_eig;   ca.dst[6] = pe_h;           ca.n8[6] = (int)((size_t)NT * C2K / 8);
    cvt_all_kernel<<<dim3(2048, 7), 256>>>(ca);

    // 1) LN1 -> fp16
    ten_ln_kernel<<<NT, 256>>>(x, n1_g, n1_b, xn_h);

    // 2) beta0 = xn @ in_proj_w^T   [16384,256] fp32 out
    mma_gemm<EPI_NONE><<<dim3(C2K/128, NT/128), 256, GEMM_SMEM>>>(
        xn_h, wh + W_INPROJ, beta0, NT, C2K, DD, nullptr, nullptr, nullptr);
    // 3) pm = prev_eig @ mem_proj_w^T  [16384,256]
    mma_gemm<EPI_NONE><<<dim3(C2K/128, NT/128), 256, GEMM_SMEM>>>(
        pe_h, wh + W_MEMPROJ, pm, NT, C2K, C2K, nullptr, nullptr, nullptr);
    // 4) gate sigmoid -> fp16 (independent of eig chain)
    mma_gemm<EPI_SIG><<<dim3(DD/128, NT/128), 256, GEMM_SMEM>>>(
        xn_h, wh + W_GATE, sig_h, NT, DD, DD, gate_b, nullptr, nullptr);

    // 5) conv + SiLU + mem inject
    ten_conv_mem_kernel<<<dim3(TT/64, C2K/32, BB), 256>>>(
        beta0, pm, conv_w, conv_b, mem_gate, bRp, bIp);
    // 6) recurrence scan
    ten_scan_kernel<<<BB * KK, 256>>>(bRp, bIp, log_decay, frequency, cRp, cIp);
    // 7) coupling -> eig fp32 (output) + fp16 copy
    ten_coupling_kernel<<<dim3(TT/256, HH, BB), 256>>>(cRp, cIp, coupling, out_eig, eig_h);

    // 8) x1 = x + sig * (eig @ out_proj^T)
    mma_gemm<EPI_GATE><<<dim3(DD/128, NT/128), 256, GEMM_SMEM>>>(
        eig_h, wh + W_OUTPROJ, x1, NT, DD, C2K, nullptr, sig_h, x);

    // 9) LN2 -> fp16
    ten_ln_kernel<<<NT, 256>>>(x1, n2_g, n2_b, y_h);

    // 10) h1 = silu(y @ w1^T + b1) fp16  [16384,4096]
    mma_gemm<EPI_SILU_H><<<dim3(MM/128, NT/128), 256, GEMM_SMEM>>>(
        y_h, wh + W_MLP1, h1_h, NT, MM, DD, mlp_b1, nullptr, nullptr);
    // 11) x2 = x1 + h1 @ w2^T + b2  [16384,1024]
    mma_gemm<EPI_BIAS_RES><<<dim3(DD/128, NT/128), 256, GEMM_SMEM>>>(
        h1_h, wh + W_MLP2, out_x2, NT, DD, MM, mlp_b2, nullptr, x1);
}